// round 2
// baseline (speedup 1.0000x reference)
#include <cuda_runtime.h>
#include <cuda_bf16.h>
#include <cstdint>

// Problem constants (max sizes for static scratch)
#define MAXN 20000
#define MAXE 320000
#define F 512        // H*HID = H*OUT = 512
#define HEADS 4
#define CH 128       // channels per head
#define NEG_BIG (-3.402823466e38f)

// ---------------- device scratch (no runtime allocation allowed) -------------
__device__ float g_q[MAXN * F];
__device__ float g_k[MAXN * F];
__device__ float g_v[MAXN * F];
__device__ float g_h[MAXN * F];
__device__ int   g_deg[MAXN];
__device__ int   g_rowptr[MAXN + 1];
__device__ int   g_cursor[MAXN];
__device__ int   g_csr[MAXE];

// ---------------- CSR build --------------------------------------------------
__global__ void count_kernel(const int* __restrict__ ei, int* __restrict__ deg, int E) {
    int e = blockIdx.x * blockDim.x + threadIdx.x;
    if (e < E) atomicAdd(&deg[ei[E + e]], 1);   // dst = edge_index[1][e]
}

__global__ void scan_kernel(const int* __restrict__ deg, int* __restrict__ rowptr,
                            int* __restrict__ cursor, int n) {
    __shared__ int sh[1024];
    __shared__ int s_carry;
    if (threadIdx.x == 0) { s_carry = 0; rowptr[0] = 0; }
    __syncthreads();
    for (int base = 0; base < n; base += 1024) {
        int i = base + threadIdx.x;
        int v = (i < n) ? deg[i] : 0;
        sh[threadIdx.x] = v;
        __syncthreads();
        for (int off = 1; off < 1024; off <<= 1) {
            int t = 0;
            if (threadIdx.x >= off) t = sh[threadIdx.x - off];
            __syncthreads();
            if (threadIdx.x >= off) sh[threadIdx.x] += t;
            __syncthreads();
        }
        int incl = sh[threadIdx.x] + s_carry;
        if (i < n) {
            rowptr[i + 1] = incl;
            cursor[i] = incl - v;   // exclusive prefix = row start
        }
        __syncthreads();
        if (threadIdx.x == 0) s_carry += sh[1023];
        __syncthreads();
    }
}

__global__ void fill_kernel(const int* __restrict__ ei, int* __restrict__ cursor,
                            int* __restrict__ csr, int E) {
    int e = blockIdx.x * blockDim.x + threadIdx.x;
    if (e < E) {
        int dst = ei[E + e];
        int pos = atomicAdd(&cursor[dst], 1);
        csr[pos] = e;
    }
}

// ---------------- GEMM: C[M,N] = A[M,K] @ W[K,N] + bias ----------------------
// 128x128 tile, BK=16, 256 threads, 8x8 per thread.
#define BM 128
#define BN 128
#define BK 16
#define TM 8
#define TN 8

__global__ __launch_bounds__(256, 2)
void gemm_bias_kernel(const float* __restrict__ A, const float* __restrict__ W,
                      const float* __restrict__ bias, float* __restrict__ C,
                      int M, int K, int N) {
    __shared__ float As[BK][BM];
    __shared__ float Bs[BK][BN];

    int tid = threadIdx.x;
    int block_row = blockIdx.y * BM;
    int block_col = blockIdx.x * BN;

    int tr = (tid >> 4) * TM;      // 0..120
    int tc = (tid & 15) * TN;      // 0..120

    float acc[TM][TN];
#pragma unroll
    for (int i = 0; i < TM; i++)
#pragma unroll
        for (int j = 0; j < TN; j++) acc[i][j] = 0.f;

    for (int k0 = 0; k0 < K; k0 += BK) {
        // Load A tile: 128 rows x 16 cols = 512 float4, 2 per thread
#pragma unroll
        for (int l = 0; l < 2; l++) {
            int idx = tid * 2 + l;          // 0..511
            int ar = idx >> 2;              // 0..127
            int ac = (idx & 3) * 4;         // 0,4,8,12
            int gr = block_row + ar;
            float4 av = make_float4(0.f, 0.f, 0.f, 0.f);
            if (gr < M) av = *(const float4*)(A + (size_t)gr * K + k0 + ac);
            As[ac + 0][ar] = av.x;
            As[ac + 1][ar] = av.y;
            As[ac + 2][ar] = av.z;
            As[ac + 3][ar] = av.w;
        }
        // Load B tile: 16 rows x 128 cols = 512 float4, 2 per thread
#pragma unroll
        for (int l = 0; l < 2; l++) {
            int idx = tid * 2 + l;
            int br = idx >> 5;              // 0..15
            int bc = (idx & 31) * 4;        // 0..124
            float4 bv = *(const float4*)(W + (size_t)(k0 + br) * N + block_col + bc);
            *(float4*)&Bs[br][bc] = bv;
        }
        __syncthreads();

#pragma unroll
        for (int kk = 0; kk < BK; kk++) {
            float a_frag[TM], b_frag[TN];
            *(float4*)&a_frag[0] = *(const float4*)&As[kk][tr];
            *(float4*)&a_frag[4] = *(const float4*)&As[kk][tr + 4];
            *(float4*)&b_frag[0] = *(const float4*)&Bs[kk][tc];
            *(float4*)&b_frag[4] = *(const float4*)&Bs[kk][tc + 4];
#pragma unroll
            for (int i = 0; i < TM; i++)
#pragma unroll
                for (int j = 0; j < TN; j++)
                    acc[i][j] += a_frag[i] * b_frag[j];
        }
        __syncthreads();
    }

    float bv[TN];
#pragma unroll
    for (int j = 0; j < TN; j++) bv[j] = bias[block_col + tc + j];

#pragma unroll
    for (int i = 0; i < TM; i++) {
        int gr = block_row + tr + i;
        if (gr < M) {
            float* cp = C + (size_t)gr * N + block_col + tc;
#pragma unroll
            for (int j = 0; j < TN; j += 4) {
                float4 r;
                r.x = acc[i][j + 0] + bv[j + 0];
                r.y = acc[i][j + 1] + bv[j + 1];
                r.z = acc[i][j + 2] + bv[j + 2];
                r.w = acc[i][j + 3] + bv[j + 3];
                *(float4*)(cp + j) = r;
            }
        }
    }
}

// ---------------- fused attention aggregation (per-dst block) ----------------
// One block per dst node, 128 threads. Warp w handles head w (4 channels/lane).
// Online softmax over incident edges; out buffer already holds skip projection.
// CONCAT=true : out stride 512, add skip + relu (layer 0)
// CONCAT=false: mean over heads into out stride 128 (layer 1)
template <bool CONCAT>
__global__ __launch_bounds__(128)
void agg_kernel(const float* __restrict__ q, const float* __restrict__ k,
                const float* __restrict__ v, const int* __restrict__ ei,
                const int* __restrict__ rowptr, const int* __restrict__ csr,
                float* __restrict__ out) {
    int row  = blockIdx.x;
    int lane = threadIdx.x & 31;
    int wid  = threadIdx.x >> 5;

    const float* qr = q + (size_t)row * F + wid * CH + lane;
    float q0 = qr[0], q1 = qr[32], q2 = qr[64], q3 = qr[96];

    float acc0 = 0.f, acc1 = 0.f, acc2 = 0.f, acc3 = 0.f;
    float m = NEG_BIG, s = 0.f;

    int start = rowptr[row], end = rowptr[row + 1];
    for (int i = start; i < end; i++) {
        int e   = csr[i];
        int src = ei[e];             // edge_index[0][e]
        const float* kp = k + (size_t)src * F + wid * CH + lane;
        const float* vp = v + (size_t)src * F + wid * CH + lane;

        float d = q0 * kp[0] + q1 * kp[32] + q2 * kp[64] + q3 * kp[96];
        d += __shfl_xor_sync(0xffffffffu, d, 16);
        d += __shfl_xor_sync(0xffffffffu, d, 8);
        d += __shfl_xor_sync(0xffffffffu, d, 4);
        d += __shfl_xor_sync(0xffffffffu, d, 2);
        d += __shfl_xor_sync(0xffffffffu, d, 1);
        float alpha = d * 0.08838834764831845f;   // 1/sqrt(128)

        float v0 = vp[0], v1 = vp[32], v2 = vp[64], v3 = vp[96];

        float mn = fmaxf(m, alpha);
        float cf = __expf(m - mn);
        float p  = __expf(alpha - mn);
        s = s * cf + p;
        acc0 = acc0 * cf + p * v0;
        acc1 = acc1 * cf + p * v1;
        acc2 = acc2 * cf + p * v2;
        acc3 = acc3 * cf + p * v3;
        m = mn;
    }

    float inv = 1.0f / (s + 1e-16f);

    if constexpr (CONCAT) {
        float* op = out + (size_t)row * F + wid * CH + lane;
        op[0]  = fmaxf(op[0]  + acc0 * inv, 0.f);
        op[32] = fmaxf(op[32] + acc1 * inv, 0.f);
        op[64] = fmaxf(op[64] + acc2 * inv, 0.f);
        op[96] = fmaxf(op[96] + acc3 * inv, 0.f);
    } else {
        __shared__ float sh[F];
        sh[wid * CH + lane +  0] = acc0 * inv;
        sh[wid * CH + lane + 32] = acc1 * inv;
        sh[wid * CH + lane + 64] = acc2 * inv;
        sh[wid * CH + lane + 96] = acc3 * inv;
        __syncthreads();
        int t = threadIdx.x;   // 0..127 = channel
        float sum = (sh[t] + sh[CH + t] + sh[2 * CH + t] + sh[3 * CH + t]) * 0.25f;
        out[(size_t)row * CH + t] += sum;
    }
}

// ---------------- launch -----------------------------------------------------
extern "C" void kernel_launch(void* const* d_in, const int* in_sizes, int n_in,
                              void* d_out, int out_size) {
    const float* x   = (const float*)d_in[0];
    const int*   ei  = (const int*)d_in[1];
    const float* Wq0 = (const float*)d_in[2];
    const float* bq0 = (const float*)d_in[3];
    const float* Wk0 = (const float*)d_in[4];
    const float* bk0 = (const float*)d_in[5];
    const float* Wv0 = (const float*)d_in[6];
    const float* bv0 = (const float*)d_in[7];
    const float* Ws0 = (const float*)d_in[8];
    const float* bs0 = (const float*)d_in[9];
    const float* Wq1 = (const float*)d_in[10];
    const float* bq1 = (const float*)d_in[11];
    const float* Wk1 = (const float*)d_in[12];
    const float* bk1 = (const float*)d_in[13];
    const float* Wv1 = (const float*)d_in[14];
    const float* bv1 = (const float*)d_in[15];
    const float* Ws1 = (const float*)d_in[16];
    const float* bs1 = (const float*)d_in[17];

    int N = in_sizes[0] / 128;     // 20000
    int E = in_sizes[1] / 2;       // 320000
    float* out = (float*)d_out;

    float *q, *k, *v, *h;
    int *deg, *rowptr, *cursor, *csr;
    cudaGetSymbolAddress((void**)&q, g_q);
    cudaGetSymbolAddress((void**)&k, g_k);
    cudaGetSymbolAddress((void**)&v, g_v);
    cudaGetSymbolAddress((void**)&h, g_h);
    cudaGetSymbolAddress((void**)&deg, g_deg);
    cudaGetSymbolAddress((void**)&rowptr, g_rowptr);
    cudaGetSymbolAddress((void**)&cursor, g_cursor);
    cudaGetSymbolAddress((void**)&csr, g_csr);

    // ---- CSR build (dst-grouped edge lists) ----
    cudaMemsetAsync(deg, 0, N * sizeof(int));
    count_kernel<<<(E + 255) / 256, 256>>>(ei, deg, E);
    scan_kernel<<<1, 1024>>>(deg, rowptr, cursor, N);
    fill_kernel<<<(E + 255) / 256, 256>>>(ei, cursor, csr, E);

    int gy = (N + BM - 1) / BM;    // 157

    // ---- Layer 0: projections (D_IN=128 -> 512) ----
    dim3 grid0(F / BN, gy);
    gemm_bias_kernel<<<grid0, 256>>>(x, Wq0, bq0, q, N, 128, F);
    gemm_bias_kernel<<<grid0, 256>>>(x, Wk0, bk0, k, N, 128, F);
    gemm_bias_kernel<<<grid0, 256>>>(x, Wv0, bv0, v, N, 128, F);
    gemm_bias_kernel<<<grid0, 256>>>(x, Ws0, bs0, h, N, 128, F);   // skip -> h
    // fused attention + skip + relu -> h
    agg_kernel<true><<<N, 128>>>(q, k, v, ei, rowptr, csr, h);

    // ---- Layer 1: projections (512 -> 512), skip (512 -> 128) ----
    gemm_bias_kernel<<<grid0, 256>>>(h, Wq1, bq1, q, N, F, F);
    gemm_bias_kernel<<<grid0, 256>>>(h, Wk1, bk1, k, N, F, F);
    gemm_bias_kernel<<<grid0, 256>>>(h, Wv1, bv1, v, N, F, F);
    dim3 grid1(CH / BN, gy);
    gemm_bias_kernel<<<grid1, 256>>>(h, Ws1, bs1, out, N, F, CH);  // skip -> out
    // fused attention (mean over heads) + skip -> out
    agg_kernel<false><<<N, 128>>>(q, k, v, ei, rowptr, csr, out);
}

// round 3
// speedup vs baseline: 1.4833x; 1.4833x over previous
#include <cuda_runtime.h>
#include <cuda_bf16.h>
#include <cstdint>

// Problem constants (max sizes for static scratch)
#define MAXN 20000
#define MAXE 320000
#define F 512        // H*HID = H*OUT = 512
#define HEADS 4
#define CH 128       // channels per head
#define NEG_BIG (-3.402823466e38f)

// ---------------- device scratch (no runtime allocation allowed) -------------
__device__ float g_q[MAXN * F];
__device__ float g_k[MAXN * F];
__device__ float g_v[MAXN * F];
__device__ float g_h[MAXN * F];
__device__ int   g_deg[MAXN];
__device__ int   g_rowptr[MAXN + 1];
__device__ int   g_cursor[MAXN];
__device__ int   g_csr[MAXE];

// ---------------- CSR build --------------------------------------------------
__global__ void count_kernel(const int* __restrict__ ei, int* __restrict__ deg, int E) {
    int e = blockIdx.x * blockDim.x + threadIdx.x;
    if (e < E) atomicAdd(&deg[ei[E + e]], 1);   // dst = edge_index[1][e]
}

__global__ void scan_kernel(const int* __restrict__ deg, int* __restrict__ rowptr,
                            int* __restrict__ cursor, int n) {
    __shared__ int sh[1024];
    __shared__ int s_carry;
    if (threadIdx.x == 0) { s_carry = 0; rowptr[0] = 0; }
    __syncthreads();
    for (int base = 0; base < n; base += 1024) {
        int i = base + threadIdx.x;
        int v = (i < n) ? deg[i] : 0;
        sh[threadIdx.x] = v;
        __syncthreads();
        for (int off = 1; off < 1024; off <<= 1) {
            int t = 0;
            if (threadIdx.x >= off) t = sh[threadIdx.x - off];
            __syncthreads();
            if (threadIdx.x >= off) sh[threadIdx.x] += t;
            __syncthreads();
        }
        int incl = sh[threadIdx.x] + s_carry;
        if (i < n) {
            rowptr[i + 1] = incl;
            cursor[i] = incl - v;   // exclusive prefix = row start
        }
        __syncthreads();
        if (threadIdx.x == 0) s_carry += sh[1023];
        __syncthreads();
    }
}

__global__ void fill_kernel(const int* __restrict__ ei, int* __restrict__ cursor,
                            int* __restrict__ csr, int E) {
    int e = blockIdx.x * blockDim.x + threadIdx.x;
    if (e < E) {
        int dst = ei[E + e];
        int pos = atomicAdd(&cursor[dst], 1);
        csr[pos] = e;
    }
}

// ---------------- tensor-core GEMM: C = A[M,K] @ W[K,N] + bias ---------------
// bf16x3 split precision: A=Ah+Al, B=Bh+Bl, D += Ah*Bh + Ah*Bl + Al*Bh.
// 128x128x32 tiles, 256 threads (2x4 warps of 64x32), mma.m16n8k16.
#define BM 128
#define BN 128
#define BKK 32
#define A_STRIDE 40    // bf16 elems per As row (pad for conflict-free ldmatrix)
#define B_STRIDE 136   // bf16 elems per Bs row

__device__ __forceinline__ void mma_bf16(float* d, const unsigned* a, const unsigned* b) {
    asm volatile(
        "mma.sync.aligned.m16n8k16.row.col.f32.bf16.bf16.f32 "
        "{%0,%1,%2,%3}, {%4,%5,%6,%7}, {%8,%9}, {%0,%1,%2,%3};"
        : "+f"(d[0]), "+f"(d[1]), "+f"(d[2]), "+f"(d[3])
        : "r"(a[0]), "r"(a[1]), "r"(a[2]), "r"(a[3]), "r"(b[0]), "r"(b[1]));
}

__device__ __forceinline__ void ldm_x4(unsigned* r, uint32_t addr) {
    asm volatile("ldmatrix.sync.aligned.m8n8.x4.shared.b16 {%0,%1,%2,%3}, [%4];"
                 : "=r"(r[0]), "=r"(r[1]), "=r"(r[2]), "=r"(r[3]) : "r"(addr));
}

__device__ __forceinline__ void ldm_x4_t(unsigned* r, uint32_t addr) {
    asm volatile("ldmatrix.sync.aligned.m8n8.x4.trans.shared.b16 {%0,%1,%2,%3}, [%4];"
                 : "=r"(r[0]), "=r"(r[1]), "=r"(r[2]), "=r"(r[3]) : "r"(addr));
}

__device__ __forceinline__ unsigned pack_hi(float x, float y) {
    __nv_bfloat162 p;
    p.x = __float2bfloat16_rn(x);
    p.y = __float2bfloat16_rn(y);
    return *(unsigned*)&p;
}

__global__ __launch_bounds__(256, 1)
void gemm_tc_kernel(const float* __restrict__ A, const float* __restrict__ W,
                    const float* __restrict__ bias, float* __restrict__ C,
                    int M, int K, int N) {
    __shared__ __nv_bfloat16 As_hi[BM][A_STRIDE];
    __shared__ __nv_bfloat16 As_lo[BM][A_STRIDE];
    __shared__ __nv_bfloat16 Bs_hi[BKK][B_STRIDE];
    __shared__ __nv_bfloat16 Bs_lo[BKK][B_STRIDE];

    int tid  = threadIdx.x;
    int lane = tid & 31;
    int wid  = tid >> 5;
    int warp_m = (wid >> 2) * 64;   // 0 or 64
    int warp_n = (wid & 3) * 32;    // 0,32,64,96

    int block_row = blockIdx.y * BM;
    int block_col = blockIdx.x * BN;

    float acc[4][4][4];
#pragma unroll
    for (int mi = 0; mi < 4; mi++)
#pragma unroll
        for (int ni = 0; ni < 4; ni++)
#pragma unroll
            for (int r = 0; r < 4; r++) acc[mi][ni][r] = 0.f;

    int Kt = K / BKK;

    // prefetch registers
    float4 pA[4], pB[4];

    // load tile 0
#pragma unroll
    for (int i = 0; i < 4; i++) {
        int idx = tid + 256 * i;
        int ar = idx >> 3;                  // 0..127
        int ac = (idx & 7) * 4;             // 0..28
        int gr = block_row + ar;
        pA[i] = (gr < M) ? *(const float4*)(A + (size_t)gr * K + ac)
                         : make_float4(0.f, 0.f, 0.f, 0.f);
        int kr = idx >> 5;                  // 0..31
        int nc = (idx & 31) * 4;            // 0..124
        pB[i] = *(const float4*)(W + (size_t)kr * N + block_col + nc);
    }

    for (int kt = 0; kt < Kt; kt++) {
        // convert + STS current tile
#pragma unroll
        for (int i = 0; i < 4; i++) {
            int idx = tid + 256 * i;
            int ar = idx >> 3;
            int ac = (idx & 7) * 4;
            float4 v = pA[i];
            float hx = __bfloat162float(__float2bfloat16_rn(v.x));
            float hy = __bfloat162float(__float2bfloat16_rn(v.y));
            float hz = __bfloat162float(__float2bfloat16_rn(v.z));
            float hw = __bfloat162float(__float2bfloat16_rn(v.w));
            *(unsigned*)&As_hi[ar][ac]     = pack_hi(v.x, v.y);
            *(unsigned*)&As_hi[ar][ac + 2] = pack_hi(v.z, v.w);
            *(unsigned*)&As_lo[ar][ac]     = pack_hi(v.x - hx, v.y - hy);
            *(unsigned*)&As_lo[ar][ac + 2] = pack_hi(v.z - hz, v.w - hw);

            int kr = idx >> 5;
            int nc = (idx & 31) * 4;
            float4 w4 = pB[i];
            float gx = __bfloat162float(__float2bfloat16_rn(w4.x));
            float gy = __bfloat162float(__float2bfloat16_rn(w4.y));
            float gz = __bfloat162float(__float2bfloat16_rn(w4.z));
            float gw = __bfloat162float(__float2bfloat16_rn(w4.w));
            *(unsigned*)&Bs_hi[kr][nc]     = pack_hi(w4.x, w4.y);
            *(unsigned*)&Bs_hi[kr][nc + 2] = pack_hi(w4.z, w4.w);
            *(unsigned*)&Bs_lo[kr][nc]     = pack_hi(w4.x - gx, w4.y - gy);
            *(unsigned*)&Bs_lo[kr][nc + 2] = pack_hi(w4.z - gz, w4.w - gw);
        }
        __syncthreads();

        // prefetch next tile
        if (kt + 1 < Kt) {
            int k0 = (kt + 1) * BKK;
#pragma unroll
            for (int i = 0; i < 4; i++) {
                int idx = tid + 256 * i;
                int ar = idx >> 3;
                int ac = (idx & 7) * 4;
                int gr = block_row + ar;
                pA[i] = (gr < M) ? *(const float4*)(A + (size_t)gr * K + k0 + ac)
                                 : make_float4(0.f, 0.f, 0.f, 0.f);
                int kr = idx >> 5;
                int nc = (idx & 31) * 4;
                pB[i] = *(const float4*)(W + (size_t)(k0 + kr) * N + block_col + nc);
            }
        }

        // compute: 2 k16 steps
#pragma unroll
        for (int ks = 0; ks < 2; ks++) {
            int kk = ks * 16;
            // B fragments: 2 x ldmatrix.x4.trans covers 4 n8-tiles (hi & lo)
            unsigned bh[8], bl[8];
#pragma unroll
            for (int nn = 0; nn < 2; nn++) {
                int q = lane >> 3;                 // quadrant
                int kr = kk + (q & 1) * 8 + (lane & 7);
                int nc = warp_n + nn * 16 + (q >> 1) * 8;
                ldm_x4_t(&bh[nn * 4], (uint32_t)__cvta_generic_to_shared(&Bs_hi[kr][nc]));
                ldm_x4_t(&bl[nn * 4], (uint32_t)__cvta_generic_to_shared(&Bs_lo[kr][nc]));
            }
#pragma unroll
            for (int mi = 0; mi < 4; mi++) {
                int r = warp_m + mi * 16 + (lane & 15);
                int c = kk + (lane >> 4) * 8;
                unsigned ah[4], al[4];
                ldm_x4(ah, (uint32_t)__cvta_generic_to_shared(&As_hi[r][c]));
                ldm_x4(al, (uint32_t)__cvta_generic_to_shared(&As_lo[r][c]));
#pragma unroll
                for (int ni = 0; ni < 4; ni++) {
                    mma_bf16(acc[mi][ni], ah, &bh[ni * 2]);
                    mma_bf16(acc[mi][ni], ah, &bl[ni * 2]);
                    mma_bf16(acc[mi][ni], al, &bh[ni * 2]);
                }
            }
        }
        __syncthreads();
    }

    // epilogue: add bias, store
    int g  = lane >> 2;
    int tg = lane & 3;
#pragma unroll
    for (int mi = 0; mi < 4; mi++) {
#pragma unroll
        for (int ni = 0; ni < 4; ni++) {
            int col = block_col + warp_n + ni * 8 + tg * 2;
            float b0 = bias[col], b1 = bias[col + 1];
            int row0 = block_row + warp_m + mi * 16 + g;
            int row1 = row0 + 8;
            if (row0 < M) {
                float2 o; o.x = acc[mi][ni][0] + b0; o.y = acc[mi][ni][1] + b1;
                *(float2*)(C + (size_t)row0 * N + col) = o;
            }
            if (row1 < M) {
                float2 o; o.x = acc[mi][ni][2] + b0; o.y = acc[mi][ni][3] + b1;
                *(float2*)(C + (size_t)row1 * N + col) = o;
            }
        }
    }
}

// ---------------- fused attention aggregation (per-dst block) ----------------
template <bool CONCAT>
__global__ __launch_bounds__(128)
void agg_kernel(const float* __restrict__ q, const float* __restrict__ k,
                const float* __restrict__ v, const int* __restrict__ ei,
                const int* __restrict__ rowptr, const int* __restrict__ csr,
                float* __restrict__ out) {
    int row  = blockIdx.x;
    int lane = threadIdx.x & 31;
    int wid  = threadIdx.x >> 5;

    const float* qr = q + (size_t)row * F + wid * CH + lane;
    float q0 = qr[0], q1 = qr[32], q2 = qr[64], q3 = qr[96];

    float acc0 = 0.f, acc1 = 0.f, acc2 = 0.f, acc3 = 0.f;
    float m = NEG_BIG, s = 0.f;

    int start = rowptr[row], end = rowptr[row + 1];
    for (int i = start; i < end; i++) {
        int e   = csr[i];
        int src = ei[e];             // edge_index[0][e]
        const float* kp = k + (size_t)src * F + wid * CH + lane;
        const float* vp = v + (size_t)src * F + wid * CH + lane;

        float d = q0 * kp[0] + q1 * kp[32] + q2 * kp[64] + q3 * kp[96];
        d += __shfl_xor_sync(0xffffffffu, d, 16);
        d += __shfl_xor_sync(0xffffffffu, d, 8);
        d += __shfl_xor_sync(0xffffffffu, d, 4);
        d += __shfl_xor_sync(0xffffffffu, d, 2);
        d += __shfl_xor_sync(0xffffffffu, d, 1);
        float alpha = d * 0.08838834764831845f;   // 1/sqrt(128)

        float v0 = vp[0], v1 = vp[32], v2 = vp[64], v3 = vp[96];

        float mn = fmaxf(m, alpha);
        float cf = __expf(m - mn);
        float p  = __expf(alpha - mn);
        s = s * cf + p;
        acc0 = acc0 * cf + p * v0;
        acc1 = acc1 * cf + p * v1;
        acc2 = acc2 * cf + p * v2;
        acc3 = acc3 * cf + p * v3;
        m = mn;
    }

    float inv = 1.0f / (s + 1e-16f);

    if constexpr (CONCAT) {
        float* op = out + (size_t)row * F + wid * CH + lane;
        op[0]  = fmaxf(op[0]  + acc0 * inv, 0.f);
        op[32] = fmaxf(op[32] + acc1 * inv, 0.f);
        op[64] = fmaxf(op[64] + acc2 * inv, 0.f);
        op[96] = fmaxf(op[96] + acc3 * inv, 0.f);
    } else {
        __shared__ float sh[F];
        sh[wid * CH + lane +  0] = acc0 * inv;
        sh[wid * CH + lane + 32] = acc1 * inv;
        sh[wid * CH + lane + 64] = acc2 * inv;
        sh[wid * CH + lane + 96] = acc3 * inv;
        __syncthreads();
        int t = threadIdx.x;   // 0..127 = channel
        float sum = (sh[t] + sh[CH + t] + sh[2 * CH + t] + sh[3 * CH + t]) * 0.25f;
        out[(size_t)row * CH + t] += sum;
    }
}

// ---------------- launch -----------------------------------------------------
extern "C" void kernel_launch(void* const* d_in, const int* in_sizes, int n_in,
                              void* d_out, int out_size) {
    const float* x   = (const float*)d_in[0];
    const int*   ei  = (const int*)d_in[1];
    const float* Wq0 = (const float*)d_in[2];
    const float* bq0 = (const float*)d_in[3];
    const float* Wk0 = (const float*)d_in[4];
    const float* bk0 = (const float*)d_in[5];
    const float* Wv0 = (const float*)d_in[6];
    const float* bv0 = (const float*)d_in[7];
    const float* Ws0 = (const float*)d_in[8];
    const float* bs0 = (const float*)d_in[9];
    const float* Wq1 = (const float*)d_in[10];
    const float* bq1 = (const float*)d_in[11];
    const float* Wk1 = (const float*)d_in[12];
    const float* bk1 = (const float*)d_in[13];
    const float* Wv1 = (const float*)d_in[14];
    const float* bv1 = (const float*)d_in[15];
    const float* Ws1 = (const float*)d_in[16];
    const float* bs1 = (const float*)d_in[17];

    int N = in_sizes[0] / 128;     // 20000
    int E = in_sizes[1] / 2;       // 320000
    float* out = (float*)d_out;

    float *q, *k, *v, *h;
    int *deg, *rowptr, *cursor, *csr;
    cudaGetSymbolAddress((void**)&q, g_q);
    cudaGetSymbolAddress((void**)&k, g_k);
    cudaGetSymbolAddress((void**)&v, g_v);
    cudaGetSymbolAddress((void**)&h, g_h);
    cudaGetSymbolAddress((void**)&deg, g_deg);
    cudaGetSymbolAddress((void**)&rowptr, g_rowptr);
    cudaGetSymbolAddress((void**)&cursor, g_cursor);
    cudaGetSymbolAddress((void**)&csr, g_csr);

    // ---- CSR build (dst-grouped edge lists) ----
    cudaMemsetAsync(deg, 0, N * sizeof(int));
    count_kernel<<<(E + 255) / 256, 256>>>(ei, deg, E);
    scan_kernel<<<1, 1024>>>(deg, rowptr, cursor, N);
    fill_kernel<<<(E + 255) / 256, 256>>>(ei, cursor, csr, E);

    int gy = (N + BM - 1) / BM;    // 157

    // ---- Layer 0: projections (D_IN=128 -> 512) ----
    dim3 grid0(F / BN, gy);
    gemm_tc_kernel<<<grid0, 256>>>(x, Wq0, bq0, q, N, 128, F);
    gemm_tc_kernel<<<grid0, 256>>>(x, Wk0, bk0, k, N, 128, F);
    gemm_tc_kernel<<<grid0, 256>>>(x, Wv0, bv0, v, N, 128, F);
    gemm_tc_kernel<<<grid0, 256>>>(x, Ws0, bs0, h, N, 128, F);   // skip -> h
    // fused attention + skip + relu -> h
    agg_kernel<true><<<N, 128>>>(q, k, v, ei, rowptr, csr, h);

    // ---- Layer 1: projections (512 -> 512), skip (512 -> 128) ----
    gemm_tc_kernel<<<grid0, 256>>>(h, Wq1, bq1, q, N, F, F);
    gemm_tc_kernel<<<grid0, 256>>>(h, Wk1, bk1, k, N, F, F);
    gemm_tc_kernel<<<grid0, 256>>>(h, Wv1, bv1, v, N, F, F);
    dim3 grid1(CH / BN, gy);
    gemm_tc_kernel<<<grid1, 256>>>(h, Ws1, bs1, out, N, F, CH);  // skip -> out
    // fused attention (mean over heads) + skip -> out
    agg_kernel<false><<<N, 128>>>(q, k, v, ei, rowptr, csr, out);
}

// round 4
// speedup vs baseline: 2.3926x; 1.6131x over previous
#include <cuda_runtime.h>
#include <cuda_bf16.h>
#include <cstdint>

// Problem constants
#define MAXN 20000
#define MAXE 320000
#define F 512
#define HEADS 4
#define CH 128
#define NEG_BIG (-3.402823466e38f)

// weight offsets in packed bf16 weight scratch
#define OQ0 0
#define OK0 65536
#define OV0 131072
#define OS0 196608
#define OQ1 262144
#define OK1 524288
#define OV1 786432
#define OS1 1048576
#define WTOT 1114112

// ---------------- device scratch ---------------------------------------------
__device__ float g_q[MAXN * F];
__device__ float g_k[MAXN * F];
__device__ float g_v[MAXN * F];
__device__ float g_h[MAXN * F];
__device__ __nv_bfloat16 g_xhi[MAXN * 128];
__device__ __nv_bfloat16 g_xlo[MAXN * 128];
__device__ __nv_bfloat16 g_hhi[MAXN * F];
__device__ __nv_bfloat16 g_hlo[MAXN * F];
__device__ __nv_bfloat16 g_wh[WTOT];
__device__ __nv_bfloat16 g_wl[WTOT];
__device__ int g_deg[MAXN];
__device__ int g_rowptr[MAXN + 1];
__device__ int g_cursor[MAXN];
__device__ int g_csr[MAXE];

// ---------------- CSR build --------------------------------------------------
__global__ void count_kernel(const int* __restrict__ ei, int* __restrict__ deg, int E) {
    int e = blockIdx.x * blockDim.x + threadIdx.x;
    if (e < E) atomicAdd(&deg[ei[E + e]], 1);
}

__global__ void scan_kernel(const int* __restrict__ deg, int* __restrict__ rowptr,
                            int* __restrict__ cursor, int n) {
    __shared__ int sh[1024];
    __shared__ int s_carry;
    if (threadIdx.x == 0) { s_carry = 0; rowptr[0] = 0; }
    __syncthreads();
    for (int base = 0; base < n; base += 1024) {
        int i = base + threadIdx.x;
        int v = (i < n) ? deg[i] : 0;
        sh[threadIdx.x] = v;
        __syncthreads();
        for (int off = 1; off < 1024; off <<= 1) {
            int t = 0;
            if (threadIdx.x >= off) t = sh[threadIdx.x - off];
            __syncthreads();
            if (threadIdx.x >= off) sh[threadIdx.x] += t;
            __syncthreads();
        }
        int incl = sh[threadIdx.x] + s_carry;
        if (i < n) {
            rowptr[i + 1] = incl;
            cursor[i] = incl - v;
        }
        __syncthreads();
        if (threadIdx.x == 0) s_carry += sh[1023];
        __syncthreads();
    }
}

// csr stores SRC node id directly (saves a dependent load in agg)
__global__ void fill_kernel(const int* __restrict__ ei, int* __restrict__ cursor,
                            int* __restrict__ csr, int E) {
    int e = blockIdx.x * blockDim.x + threadIdx.x;
    if (e < E) {
        int dst = ei[E + e];
        int pos = atomicAdd(&cursor[dst], 1);
        csr[pos] = ei[e];
    }
}

// ---------------- fp32 -> bf16 hi/lo split -----------------------------------
__device__ __forceinline__ unsigned pack2(float x, float y) {
    __nv_bfloat162 p;
    p.x = __float2bfloat16_rn(x);
    p.y = __float2bfloat16_rn(y);
    return *(unsigned*)&p;
}

__global__ void split_kernel(const float* __restrict__ in,
                             __nv_bfloat16* __restrict__ hi,
                             __nv_bfloat16* __restrict__ lo, int n4) {
    int i = blockIdx.x * blockDim.x + threadIdx.x;
    if (i < n4) {
        float4 v = ((const float4*)in)[i];
        float hx = __bfloat162float(__float2bfloat16_rn(v.x));
        float hy = __bfloat162float(__float2bfloat16_rn(v.y));
        float hz = __bfloat162float(__float2bfloat16_rn(v.z));
        float hw = __bfloat162float(__float2bfloat16_rn(v.w));
        uint2 h2, l2;
        h2.x = pack2(v.x, v.y);       h2.y = pack2(v.z, v.w);
        l2.x = pack2(v.x - hx, v.y - hy);
        l2.y = pack2(v.z - hz, v.w - hw);
        ((uint2*)hi)[i] = h2;
        ((uint2*)lo)[i] = l2;
    }
}

// ---------------- tensor-core GEMM (bf16x3, pre-split inputs) ----------------
// C[M,N] = A @ W + bias.  128x128x32 tiles, 256 thr, cp.async double-buffer.
#define BM 128
#define BN 128
#define BKK 32
#define A_STRIDE 40
#define B_STRIDE 136
#define GEMM_SMEM ((2 * BM * A_STRIDE * 2 + 2 * BKK * B_STRIDE * 2) * 2)  // 75776 B

__device__ __forceinline__ void mma_bf16(float* d, const unsigned* a, const unsigned* b) {
    asm volatile(
        "mma.sync.aligned.m16n8k16.row.col.f32.bf16.bf16.f32 "
        "{%0,%1,%2,%3}, {%4,%5,%6,%7}, {%8,%9}, {%0,%1,%2,%3};"
        : "+f"(d[0]), "+f"(d[1]), "+f"(d[2]), "+f"(d[3])
        : "r"(a[0]), "r"(a[1]), "r"(a[2]), "r"(a[3]), "r"(b[0]), "r"(b[1]));
}
__device__ __forceinline__ void ldm_x4(unsigned* r, uint32_t addr) {
    asm volatile("ldmatrix.sync.aligned.m8n8.x4.shared.b16 {%0,%1,%2,%3}, [%4];"
                 : "=r"(r[0]), "=r"(r[1]), "=r"(r[2]), "=r"(r[3]) : "r"(addr));
}
__device__ __forceinline__ void ldm_x4_t(unsigned* r, uint32_t addr) {
    asm volatile("ldmatrix.sync.aligned.m8n8.x4.trans.shared.b16 {%0,%1,%2,%3}, [%4];"
                 : "=r"(r[0]), "=r"(r[1]), "=r"(r[2]), "=r"(r[3]) : "r"(addr));
}
__device__ __forceinline__ void cp16(uint32_t dst, const void* src, bool pred) {
    int sz = pred ? 16 : 0;
    asm volatile("cp.async.cg.shared.global [%0], [%1], 16, %2;\n"
                 :: "r"(dst), "l"(src), "r"(sz));
}
#define CP_COMMIT() asm volatile("cp.async.commit_group;\n" ::: "memory")
#define CP_WAIT(n)  asm volatile("cp.async.wait_group %0;\n" :: "n"(n) : "memory")

__global__ __launch_bounds__(256, 2)
void gemm_tc_kernel(const __nv_bfloat16* __restrict__ Ah, const __nv_bfloat16* __restrict__ Al,
                    const __nv_bfloat16* __restrict__ Wh, const __nv_bfloat16* __restrict__ Wl,
                    const float* __restrict__ bias, float* __restrict__ C,
                    int M, int K, int N) {
    extern __shared__ __nv_bfloat16 smem[];
    __nv_bfloat16* As_hi = smem;                              // [2][BM][A_STRIDE]
    __nv_bfloat16* As_lo = As_hi + 2 * BM * A_STRIDE;
    __nv_bfloat16* Bs_hi = As_lo + 2 * BM * A_STRIDE;         // [2][BKK][B_STRIDE]
    __nv_bfloat16* Bs_lo = Bs_hi + 2 * BKK * B_STRIDE;

    int tid  = threadIdx.x;
    int lane = tid & 31;
    int wid  = tid >> 5;
    int warp_m = (wid >> 2) * 64;
    int warp_n = (wid & 3) * 32;
    int block_row = blockIdx.y * BM;
    int block_col = blockIdx.x * BN;

    float acc[4][4][4];
#pragma unroll
    for (int mi = 0; mi < 4; mi++)
#pragma unroll
        for (int ni = 0; ni < 4; ni++)
#pragma unroll
            for (int r = 0; r < 4; r++) acc[mi][ni][r] = 0.f;

    int Kt = K / BKK;

    auto load_stage = [&](int s, int kt) {
        int k0 = kt * BKK;
        __nv_bfloat16* ah = As_hi + s * BM * A_STRIDE;
        __nv_bfloat16* al = As_lo + s * BM * A_STRIDE;
        __nv_bfloat16* bh = Bs_hi + s * BKK * B_STRIDE;
        __nv_bfloat16* bl = Bs_lo + s * BKK * B_STRIDE;
#pragma unroll
        for (int l = 0; l < 2; l++) {
            int idx = tid + 256 * l;            // 0..511
            int ar = idx >> 2;                  // 0..127
            int ac = (idx & 3) * 8;             // 0..24
            int gr = block_row + ar;
            bool ok = gr < M;
            size_t go = (size_t)gr * K + k0 + ac;
            cp16((uint32_t)__cvta_generic_to_shared(&ah[ar * A_STRIDE + ac]), Ah + go, ok);
            cp16((uint32_t)__cvta_generic_to_shared(&al[ar * A_STRIDE + ac]), Al + go, ok);
            int kr = idx >> 4;                  // 0..31
            int nc = (idx & 15) * 8;            // 0..120
            size_t wo = (size_t)(k0 + kr) * N + block_col + nc;
            cp16((uint32_t)__cvta_generic_to_shared(&bh[kr * B_STRIDE + nc]), Wh + wo, true);
            cp16((uint32_t)__cvta_generic_to_shared(&bl[kr * B_STRIDE + nc]), Wl + wo, true);
        }
    };

    load_stage(0, 0);
    CP_COMMIT();

    for (int kt = 0; kt < Kt; kt++) {
        int s = kt & 1;
        if (kt + 1 < Kt) {
            load_stage((kt + 1) & 1, kt + 1);
            CP_COMMIT();
            CP_WAIT(1);
        } else {
            CP_WAIT(0);
        }
        __syncthreads();

        const __nv_bfloat16* ah_s = As_hi + s * BM * A_STRIDE;
        const __nv_bfloat16* al_s = As_lo + s * BM * A_STRIDE;
        const __nv_bfloat16* bh_s = Bs_hi + s * BKK * B_STRIDE;
        const __nv_bfloat16* bl_s = Bs_lo + s * BKK * B_STRIDE;

#pragma unroll
        for (int ks = 0; ks < 2; ks++) {
            int kk = ks * 16;
            unsigned bh[8], bl[8];
#pragma unroll
            for (int nn = 0; nn < 2; nn++) {
                int q = lane >> 3;
                int kr = kk + (q & 1) * 8 + (lane & 7);
                int nc = warp_n + nn * 16 + (q >> 1) * 8;
                ldm_x4_t(&bh[nn * 4], (uint32_t)__cvta_generic_to_shared(&bh_s[kr * B_STRIDE + nc]));
                ldm_x4_t(&bl[nn * 4], (uint32_t)__cvta_generic_to_shared(&bl_s[kr * B_STRIDE + nc]));
            }
#pragma unroll
            for (int mi = 0; mi < 4; mi++) {
                int r = warp_m + mi * 16 + (lane & 15);
                int c = kk + (lane >> 4) * 8;
                unsigned ah[4], al[4];
                ldm_x4(ah, (uint32_t)__cvta_generic_to_shared(&ah_s[r * A_STRIDE + c]));
                ldm_x4(al, (uint32_t)__cvta_generic_to_shared(&al_s[r * A_STRIDE + c]));
#pragma unroll
                for (int ni = 0; ni < 4; ni++) {
                    mma_bf16(acc[mi][ni], ah, &bh[ni * 2]);
                    mma_bf16(acc[mi][ni], ah, &bl[ni * 2]);
                    mma_bf16(acc[mi][ni], al, &bh[ni * 2]);
                }
            }
        }
        __syncthreads();
    }

    // epilogue
    int g  = lane >> 2;
    int tg = lane & 3;
#pragma unroll
    for (int mi = 0; mi < 4; mi++) {
#pragma unroll
        for (int ni = 0; ni < 4; ni++) {
            int col = block_col + warp_n + ni * 8 + tg * 2;
            float b0 = bias[col], b1 = bias[col + 1];
            int row0 = block_row + warp_m + mi * 16 + g;
            int row1 = row0 + 8;
            if (row0 < M) {
                float2 o; o.x = acc[mi][ni][0] + b0; o.y = acc[mi][ni][1] + b1;
                *(float2*)(C + (size_t)row0 * N + col) = o;
            }
            if (row1 < M) {
                float2 o; o.x = acc[mi][ni][2] + b0; o.y = acc[mi][ni][3] + b1;
                *(float2*)(C + (size_t)row1 * N + col) = o;
            }
        }
    }
}

// ---------------- fused attention aggregation --------------------------------
// One block per dst node, 128 threads (warp = head). Chunk-of-4 online softmax
// for ILP across the shfl-reduce and gather chains.
// CONCAT=true : reads fp32 skip, writes relu(skip+attn) as bf16 hi/lo (layer 0)
// CONCAT=false: mean over heads, accumulates into fp32 out (layer 1)
template <bool CONCAT>
__global__ __launch_bounds__(128)
void agg_kernel(const float* __restrict__ q, const float* __restrict__ k,
                const float* __restrict__ v,
                const int* __restrict__ rowptr, const int* __restrict__ csr,
                const float* __restrict__ skip,
                float* __restrict__ out,
                __nv_bfloat16* __restrict__ ohi, __nv_bfloat16* __restrict__ olo) {
    int row  = blockIdx.x;
    int lane = threadIdx.x & 31;
    int wid  = threadIdx.x >> 5;
    int off  = wid * CH + lane;

    const float* qr = q + (size_t)row * F + off;
    float q0 = qr[0], q1 = qr[32], q2 = qr[64], q3 = qr[96];

    float a0 = 0.f, a1 = 0.f, a2 = 0.f, a3 = 0.f;
    float m = NEG_BIG, s = 0.f;

    int start = rowptr[row], end = rowptr[row + 1];
    int i = start;
    while (i < end) {
        int rem = end - i;
        int c = rem < 4 ? rem : 4;
        int srcs[4];
        float dt[4];
#pragma unroll
        for (int j = 0; j < 4; j++)
            srcs[j] = csr[i + (j < c ? j : c - 1)];
#pragma unroll
        for (int j = 0; j < 4; j++) {
            const float* kp = k + (size_t)srcs[j] * F + off;
            dt[j] = q0 * kp[0] + q1 * kp[32] + q2 * kp[64] + q3 * kp[96];
        }
#pragma unroll
        for (int o = 16; o >= 1; o >>= 1)
#pragma unroll
            for (int j = 0; j < 4; j++)
                dt[j] += __shfl_xor_sync(0xffffffffu, dt[j], o);

        // gather v rows with ILP
        float v0[4], v1[4], v2[4], v3[4];
#pragma unroll
        for (int j = 0; j < 4; j++) {
            const float* vp = v + (size_t)srcs[j] * F + off;
            v0[j] = vp[0]; v1[j] = vp[32]; v2[j] = vp[64]; v3[j] = vp[96];
        }

#pragma unroll
        for (int j = 0; j < 4; j++) {
            dt[j] = (j < c) ? dt[j] * 0.08838834764831845f : NEG_BIG;
        }
        float cm = fmaxf(fmaxf(dt[0], dt[1]), fmaxf(dt[2], dt[3]));
        float mn = fmaxf(m, cm);
        float cf = __expf(m - mn);
        s *= cf; a0 *= cf; a1 *= cf; a2 *= cf; a3 *= cf;
#pragma unroll
        for (int j = 0; j < 4; j++) {
            if (j < c) {
                float p = __expf(dt[j] - mn);
                s += p;
                a0 += p * v0[j]; a1 += p * v1[j];
                a2 += p * v2[j]; a3 += p * v3[j];
            }
        }
        m = mn;
        i += c;
    }

    float inv = 1.0f / (s + 1e-16f);

    if constexpr (CONCAT) {
        const float* sp = skip + (size_t)row * F + off;
        float r0 = fmaxf(sp[0]  + a0 * inv, 0.f);
        float r1 = fmaxf(sp[32] + a1 * inv, 0.f);
        float r2 = fmaxf(sp[64] + a2 * inv, 0.f);
        float r3 = fmaxf(sp[96] + a3 * inv, 0.f);
        size_t ob = (size_t)row * F + off;
        __nv_bfloat16 h0 = __float2bfloat16_rn(r0);
        __nv_bfloat16 h1 = __float2bfloat16_rn(r1);
        __nv_bfloat16 h2 = __float2bfloat16_rn(r2);
        __nv_bfloat16 h3 = __float2bfloat16_rn(r3);
        ohi[ob]      = h0; ohi[ob + 32] = h1; ohi[ob + 64] = h2; ohi[ob + 96] = h3;
        olo[ob]      = __float2bfloat16_rn(r0 - __bfloat162float(h0));
        olo[ob + 32] = __float2bfloat16_rn(r1 - __bfloat162float(h1));
        olo[ob + 64] = __float2bfloat16_rn(r2 - __bfloat162float(h2));
        olo[ob + 96] = __float2bfloat16_rn(r3 - __bfloat162float(h3));
    } else {
        __shared__ float sh[F];
        sh[off]      = a0 * inv;
        sh[off + 32] = a1 * inv;
        sh[off + 64] = a2 * inv;
        sh[off + 96] = a3 * inv;
        __syncthreads();
        int t = threadIdx.x;
        float sum = (sh[t] + sh[CH + t] + sh[2 * CH + t] + sh[3 * CH + t]) * 0.25f;
        out[(size_t)row * CH + t] += sum;
    }
}

// ---------------- launch -----------------------------------------------------
extern "C" void kernel_launch(void* const* d_in, const int* in_sizes, int n_in,
                              void* d_out, int out_size) {
    const float* x   = (const float*)d_in[0];
    const int*   ei  = (const int*)d_in[1];
    const float* Wq0 = (const float*)d_in[2];
    const float* bq0 = (const float*)d_in[3];
    const float* Wk0 = (const float*)d_in[4];
    const float* bk0 = (const float*)d_in[5];
    const float* Wv0 = (const float*)d_in[6];
    const float* bv0 = (const float*)d_in[7];
    const float* Ws0 = (const float*)d_in[8];
    const float* bs0 = (const float*)d_in[9];
    const float* Wq1 = (const float*)d_in[10];
    const float* bq1 = (const float*)d_in[11];
    const float* Wk1 = (const float*)d_in[12];
    const float* bk1 = (const float*)d_in[13];
    const float* Wv1 = (const float*)d_in[14];
    const float* bv1 = (const float*)d_in[15];
    const float* Ws1 = (const float*)d_in[16];
    const float* bs1 = (const float*)d_in[17];

    int N = in_sizes[0] / 128;     // 20000
    int E = in_sizes[1] / 2;       // 320000
    float* out = (float*)d_out;

    float *q, *k, *v, *h;
    __nv_bfloat16 *xhi, *xlo, *hhi, *hlo, *wh, *wl;
    int *deg, *rowptr, *cursor, *csr;
    cudaGetSymbolAddress((void**)&q, g_q);
    cudaGetSymbolAddress((void**)&k, g_k);
    cudaGetSymbolAddress((void**)&v, g_v);
    cudaGetSymbolAddress((void**)&h, g_h);
    cudaGetSymbolAddress((void**)&xhi, g_xhi);
    cudaGetSymbolAddress((void**)&xlo, g_xlo);
    cudaGetSymbolAddress((void**)&hhi, g_hhi);
    cudaGetSymbolAddress((void**)&hlo, g_hlo);
    cudaGetSymbolAddress((void**)&wh, g_wh);
    cudaGetSymbolAddress((void**)&wl, g_wl);
    cudaGetSymbolAddress((void**)&deg, g_deg);
    cudaGetSymbolAddress((void**)&rowptr, g_rowptr);
    cudaGetSymbolAddress((void**)&cursor, g_cursor);
    cudaGetSymbolAddress((void**)&csr, g_csr);

    cudaFuncSetAttribute(gemm_tc_kernel, cudaFuncAttributeMaxDynamicSharedMemorySize, GEMM_SMEM);

    // ---- CSR build ----
    cudaMemsetAsync(deg, 0, N * sizeof(int));
    count_kernel<<<(E + 255) / 256, 256>>>(ei, deg, E);
    scan_kernel<<<1, 1024>>>(deg, rowptr, cursor, N);
    fill_kernel<<<(E + 255) / 256, 256>>>(ei, cursor, csr, E);

    // ---- pre-split inputs/weights to bf16 hi/lo ----
    auto split = [&](const float* src, __nv_bfloat16* hi, __nv_bfloat16* lo, int n) {
        int n4 = n / 4;
        split_kernel<<<(n4 + 255) / 256, 256>>>(src, hi, lo, n4);
    };
    split(x, xhi, xlo, N * 128);
    split(Wq0, wh + OQ0, wl + OQ0, 128 * 512);
    split(Wk0, wh + OK0, wl + OK0, 128 * 512);
    split(Wv0, wh + OV0, wl + OV0, 128 * 512);
    split(Ws0, wh + OS0, wl + OS0, 128 * 512);
    split(Wq1, wh + OQ1, wl + OQ1, 512 * 512);
    split(Wk1, wh + OK1, wl + OK1, 512 * 512);
    split(Wv1, wh + OV1, wl + OV1, 512 * 512);
    split(Ws1, wh + OS1, wl + OS1, 512 * 128);

    int gy = (N + BM - 1) / BM;    // 157

    // ---- Layer 0 (K=128) ----
    dim3 grid0(F / BN, gy);
    gemm_tc_kernel<<<grid0, 256, GEMM_SMEM>>>(xhi, xlo, wh + OQ0, wl + OQ0, bq0, q, N, 128, F);
    gemm_tc_kernel<<<grid0, 256, GEMM_SMEM>>>(xhi, xlo, wh + OK0, wl + OK0, bk0, k, N, 128, F);
    gemm_tc_kernel<<<grid0, 256, GEMM_SMEM>>>(xhi, xlo, wh + OV0, wl + OV0, bv0, v, N, 128, F);
    gemm_tc_kernel<<<grid0, 256, GEMM_SMEM>>>(xhi, xlo, wh + OS0, wl + OS0, bs0, h, N, 128, F);
    agg_kernel<true><<<N, 128>>>(q, k, v, rowptr, csr, h, nullptr, hhi, hlo);

    // ---- Layer 1 (K=512) ----
    gemm_tc_kernel<<<grid0, 256, GEMM_SMEM>>>(hhi, hlo, wh + OQ1, wl + OQ1, bq1, q, N, F, F);
    gemm_tc_kernel<<<grid0, 256, GEMM_SMEM>>>(hhi, hlo, wh + OK1, wl + OK1, bk1, k, N, F, F);
    gemm_tc_kernel<<<grid0, 256, GEMM_SMEM>>>(hhi, hlo, wh + OV1, wl + OV1, bv1, v, N, F, F);
    dim3 grid1(CH / BN, gy);
    gemm_tc_kernel<<<grid1, 256, GEMM_SMEM>>>(hhi, hlo, wh + OS1, wl + OS1, bs1, out, N, F, CH);
    agg_kernel<false><<<N, 128>>>(q, k, v, rowptr, csr, nullptr, out, nullptr, nullptr);
}

// round 7
// speedup vs baseline: 2.9894x; 1.2494x over previous
#include <cuda_runtime.h>
#include <cuda_bf16.h>
#include <cstdint>

// Problem constants
#define MAXN 20000
#define MAXE 320000
#define F 512
#define CH 128
#define NEG_BIG (-3.402823466e38f)

// weight offsets in packed bf16 weight scratch (elements)
#define OQ0 0
#define OK0 65536
#define OV0 131072
#define OS0 196608
#define OQ1 262144
#define OK1 524288
#define OV1 786432
#define OS1 1048576
#define WTOT 1114112

// ---------------- device scratch ---------------------------------------------
__device__ float g_q[MAXN * F];                 // q (fp32, both layers)
__device__ __nv_bfloat16 g_kb[MAXN * F];        // k (bf16)
__device__ __nv_bfloat16 g_vb[MAXN * F];        // v (bf16)
__device__ float g_h[MAXN * F];                 // layer-0 skip / hidden fp32
__device__ __nv_bfloat16 g_xhi[MAXN * 128];
__device__ __nv_bfloat16 g_xlo[MAXN * 128];
__device__ __nv_bfloat16 g_hhi[MAXN * F];
__device__ __nv_bfloat16 g_hlo[MAXN * F];
__device__ __nv_bfloat16 g_wh[WTOT];
__device__ __nv_bfloat16 g_wl[WTOT];
__device__ int g_deg[MAXN];
__device__ int g_rowptr[MAXN + 1];
__device__ int g_cursor[MAXN];
__device__ int g_csr[MAXE];

// ---------------- CSR build --------------------------------------------------
__global__ void count_kernel(const int* __restrict__ ei, int* __restrict__ deg, int E) {
    int e = blockIdx.x * blockDim.x + threadIdx.x;
    if (e < E) atomicAdd(&deg[ei[E + e]], 1);
}

__global__ void scan_kernel(const int* __restrict__ deg, int* __restrict__ rowptr,
                            int* __restrict__ cursor, int n) {
    __shared__ int sh[1024];
    __shared__ int s_carry;
    if (threadIdx.x == 0) { s_carry = 0; rowptr[0] = 0; }
    __syncthreads();
    for (int base = 0; base < n; base += 1024) {
        int i = base + threadIdx.x;
        int v = (i < n) ? deg[i] : 0;
        sh[threadIdx.x] = v;
        __syncthreads();
        for (int off = 1; off < 1024; off <<= 1) {
            int t = 0;
            if (threadIdx.x >= off) t = sh[threadIdx.x - off];
            __syncthreads();
            if (threadIdx.x >= off) sh[threadIdx.x] += t;
            __syncthreads();
        }
        int incl = sh[threadIdx.x] + s_carry;
        if (i < n) {
            rowptr[i + 1] = incl;
            cursor[i] = incl - v;
        }
        __syncthreads();
        if (threadIdx.x == 0) s_carry += sh[1023];
        __syncthreads();
    }
}

__global__ void fill_kernel(const int* __restrict__ ei, int* __restrict__ cursor,
                            int* __restrict__ csr, int E) {
    int e = blockIdx.x * blockDim.x + threadIdx.x;
    if (e < E) {
        int dst = ei[E + e];
        int pos = atomicAdd(&cursor[dst], 1);
        csr[pos] = ei[e];   // store src id directly
    }
}

// ---------------- batched fp32 -> bf16 hi/lo split ---------------------------
struct SplitBatch {
    const float* in[9];
    __nv_bfloat16* hi[9];
    __nv_bfloat16* lo[9];
    int n4[9];
};

__global__ void splitb_kernel(SplitBatch p) {
    int z = blockIdx.z;
    int i = blockIdx.x * blockDim.x + threadIdx.x;
    if (i >= p.n4[z]) return;
    float4 v = ((const float4*)p.in[z])[i];
    __nv_bfloat162 h0, h1, l0, l1;
    h0.x = __float2bfloat16_rn(v.x); h0.y = __float2bfloat16_rn(v.y);
    h1.x = __float2bfloat16_rn(v.z); h1.y = __float2bfloat16_rn(v.w);
    l0.x = __float2bfloat16_rn(v.x - __bfloat162float(h0.x));
    l0.y = __float2bfloat16_rn(v.y - __bfloat162float(h0.y));
    l1.x = __float2bfloat16_rn(v.z - __bfloat162float(h1.x));
    l1.y = __float2bfloat16_rn(v.w - __bfloat162float(h1.y));
    uint2 hh, ll;
    hh.x = *(unsigned*)&h0; hh.y = *(unsigned*)&h1;
    ll.x = *(unsigned*)&l0; ll.y = *(unsigned*)&l1;
    ((uint2*)p.hi[z])[i] = hh;
    ((uint2*)p.lo[z])[i] = ll;
}

// ---------------- tensor-core GEMM (bf16x3, z-batched) -----------------------
// C[M,N] = A @ W + bias.  128x128x32 tiles, 256 thr, cp.async double-buffer.
#define BM 128
#define BN 128
#define BKK 32
#define A_STRIDE 40
#define B_STRIDE 136
#define GEMM_SMEM ((2 * BM * A_STRIDE * 2 + 2 * BKK * B_STRIDE * 2) * 2)  // 75776 B

__device__ __forceinline__ void mma_bf16(float* d, const unsigned* a, const unsigned* b) {
    asm volatile(
        "mma.sync.aligned.m16n8k16.row.col.f32.bf16.bf16.f32 "
        "{%0,%1,%2,%3}, {%4,%5,%6,%7}, {%8,%9}, {%0,%1,%2,%3};"
        : "+f"(d[0]), "+f"(d[1]), "+f"(d[2]), "+f"(d[3])
        : "r"(a[0]), "r"(a[1]), "r"(a[2]), "r"(a[3]), "r"(b[0]), "r"(b[1]));
}
__device__ __forceinline__ void ldm_x4(unsigned* r, uint32_t addr) {
    asm volatile("ldmatrix.sync.aligned.m8n8.x4.shared.b16 {%0,%1,%2,%3}, [%4];"
                 : "=r"(r[0]), "=r"(r[1]), "=r"(r[2]), "=r"(r[3]) : "r"(addr));
}
__device__ __forceinline__ void ldm_x4_t(unsigned* r, uint32_t addr) {
    asm volatile("ldmatrix.sync.aligned.m8n8.x4.trans.shared.b16 {%0,%1,%2,%3}, [%4];"
                 : "=r"(r[0]), "=r"(r[1]), "=r"(r[2]), "=r"(r[3]) : "r"(addr));
}
__device__ __forceinline__ void cp16(uint32_t dst, const void* src, bool pred) {
    int sz = pred ? 16 : 0;
    asm volatile("cp.async.cg.shared.global [%0], [%1], 16, %2;\n"
                 :: "r"(dst), "l"(src), "r"(sz));
}
#define CP_COMMIT() asm volatile("cp.async.commit_group;\n" ::: "memory")
#define CP_WAIT(n)  asm volatile("cp.async.wait_group %0;\n" :: "n"(n) : "memory")

struct GemmBatch {
    const __nv_bfloat16* Ah;
    const __nv_bfloat16* Al;
    const __nv_bfloat16* Wh[4];
    const __nv_bfloat16* Wl[4];
    const float* bias[4];
    void* C[4];
    unsigned bfmask;   // bit z set -> output bf16, else fp32
};

__global__ __launch_bounds__(256, 2)
void gemm_tc_kernel(GemmBatch p, int M, int K, int N) {
    extern __shared__ __nv_bfloat16 smem[];
    __nv_bfloat16* As_hi = smem;                              // [2][BM][A_STRIDE]
    __nv_bfloat16* As_lo = As_hi + 2 * BM * A_STRIDE;
    __nv_bfloat16* Bs_hi = As_lo + 2 * BM * A_STRIDE;         // [2][BKK][B_STRIDE]
    __nv_bfloat16* Bs_lo = Bs_hi + 2 * BKK * B_STRIDE;

    int z = blockIdx.z;
    const __nv_bfloat16* Ah = p.Ah;
    const __nv_bfloat16* Al = p.Al;
    const __nv_bfloat16* Wh = p.Wh[z];
    const __nv_bfloat16* Wl = p.Wl[z];
    const float* bias = p.bias[z];
    bool obf = (p.bfmask >> z) & 1u;
    float* Cf = (float*)p.C[z];
    __nv_bfloat16* Cb = (__nv_bfloat16*)p.C[z];

    int tid  = threadIdx.x;
    int lane = tid & 31;
    int wid  = tid >> 5;
    int warp_m = (wid >> 2) * 64;
    int warp_n = (wid & 3) * 32;
    int block_row = blockIdx.y * BM;
    int block_col = blockIdx.x * BN;

    float acc[4][4][4];
#pragma unroll
    for (int mi = 0; mi < 4; mi++)
#pragma unroll
        for (int ni = 0; ni < 4; ni++)
#pragma unroll
            for (int r = 0; r < 4; r++) acc[mi][ni][r] = 0.f;

    int Kt = K / BKK;

    auto load_stage = [&](int s, int kt) {
        int k0 = kt * BKK;
        __nv_bfloat16* ah = As_hi + s * BM * A_STRIDE;
        __nv_bfloat16* al = As_lo + s * BM * A_STRIDE;
        __nv_bfloat16* bh = Bs_hi + s * BKK * B_STRIDE;
        __nv_bfloat16* bl = Bs_lo + s * BKK * B_STRIDE;
#pragma unroll
        for (int l = 0; l < 2; l++) {
            int idx = tid + 256 * l;            // 0..511
            int ar = idx >> 2;                  // 0..127
            int ac = (idx & 3) * 8;             // 0..24
            int gr = block_row + ar;
            bool ok = gr < M;
            size_t go = (size_t)gr * K + k0 + ac;
            cp16((uint32_t)__cvta_generic_to_shared(&ah[ar * A_STRIDE + ac]), Ah + go, ok);
            cp16((uint32_t)__cvta_generic_to_shared(&al[ar * A_STRIDE + ac]), Al + go, ok);
            int kr = idx >> 4;                  // 0..31
            int nc = (idx & 15) * 8;            // 0..120
            size_t wo = (size_t)(k0 + kr) * N + block_col + nc;
            cp16((uint32_t)__cvta_generic_to_shared(&bh[kr * B_STRIDE + nc]), Wh + wo, true);
            cp16((uint32_t)__cvta_generic_to_shared(&bl[kr * B_STRIDE + nc]), Wl + wo, true);
        }
    };

    load_stage(0, 0);
    CP_COMMIT();

    for (int kt = 0; kt < Kt; kt++) {
        int s = kt & 1;
        if (kt + 1 < Kt) {
            load_stage((kt + 1) & 1, kt + 1);
            CP_COMMIT();
            CP_WAIT(1);
        } else {
            CP_WAIT(0);
        }
        __syncthreads();

        const __nv_bfloat16* ah_s = As_hi + s * BM * A_STRIDE;
        const __nv_bfloat16* al_s = As_lo + s * BM * A_STRIDE;
        const __nv_bfloat16* bh_s = Bs_hi + s * BKK * B_STRIDE;
        const __nv_bfloat16* bl_s = Bs_lo + s * BKK * B_STRIDE;

#pragma unroll
        for (int ks = 0; ks < 2; ks++) {
            int kk = ks * 16;
            unsigned bh[8], bl[8];
#pragma unroll
            for (int nn = 0; nn < 2; nn++) {
                int qd = lane >> 3;
                int kr = kk + (qd & 1) * 8 + (lane & 7);
                int nc = warp_n + nn * 16 + (qd >> 1) * 8;
                ldm_x4_t(&bh[nn * 4], (uint32_t)__cvta_generic_to_shared(&bh_s[kr * B_STRIDE + nc]));
                ldm_x4_t(&bl[nn * 4], (uint32_t)__cvta_generic_to_shared(&bl_s[kr * B_STRIDE + nc]));
            }
#pragma unroll
            for (int mi = 0; mi < 4; mi++) {
                int r = warp_m + mi * 16 + (lane & 15);
                int c = kk + (lane >> 4) * 8;
                unsigned ah[4], al[4];
                ldm_x4(ah, (uint32_t)__cvta_generic_to_shared(&ah_s[r * A_STRIDE + c]));
                ldm_x4(al, (uint32_t)__cvta_generic_to_shared(&al_s[r * A_STRIDE + c]));
#pragma unroll
                for (int ni = 0; ni < 4; ni++) {
                    mma_bf16(acc[mi][ni], ah, &bh[ni * 2]);
                    mma_bf16(acc[mi][ni], ah, &bl[ni * 2]);
                    mma_bf16(acc[mi][ni], al, &bh[ni * 2]);
                }
            }
        }
        __syncthreads();
    }

    // epilogue: bias + store (fp32 or bf16 per z)
    int g  = lane >> 2;
    int tg = lane & 3;
#pragma unroll
    for (int mi = 0; mi < 4; mi++) {
#pragma unroll
        for (int ni = 0; ni < 4; ni++) {
            int col = block_col + warp_n + ni * 8 + tg * 2;
            float b0 = bias[col], b1 = bias[col + 1];
            int row0 = block_row + warp_m + mi * 16 + g;
            int row1 = row0 + 8;
            float o00 = acc[mi][ni][0] + b0, o01 = acc[mi][ni][1] + b1;
            float o10 = acc[mi][ni][2] + b0, o11 = acc[mi][ni][3] + b1;
            if (obf) {
                if (row0 < M) {
                    __nv_bfloat162 pr;
                    pr.x = __float2bfloat16_rn(o00); pr.y = __float2bfloat16_rn(o01);
                    *(__nv_bfloat162*)(Cb + (size_t)row0 * N + col) = pr;
                }
                if (row1 < M) {
                    __nv_bfloat162 pr;
                    pr.x = __float2bfloat16_rn(o10); pr.y = __float2bfloat16_rn(o11);
                    *(__nv_bfloat162*)(Cb + (size_t)row1 * N + col) = pr;
                }
            } else {
                if (row0 < M) {
                    float2 o; o.x = o00; o.y = o01;
                    *(float2*)(Cf + (size_t)row0 * N + col) = o;
                }
                if (row1 < M) {
                    float2 o; o.x = o10; o.y = o11;
                    *(float2*)(Cf + (size_t)row1 * N + col) = o;
                }
            }
        }
    }
}

// ---------------- fused attention aggregation --------------------------------
// One block per dst node, 128 threads (warp = head). Lane owns 4 CONTIGUOUS
// channels; k/v are bf16 (one 8B load per lane per row).
template <bool CONCAT>
__global__ __launch_bounds__(128)
void agg_kernel(const float* __restrict__ q, const __nv_bfloat16* __restrict__ kb,
                const __nv_bfloat16* __restrict__ vb,
                const int* __restrict__ rowptr, const int* __restrict__ csr,
                const float* __restrict__ skip,
                float* __restrict__ out,
                __nv_bfloat16* __restrict__ ohi, __nv_bfloat16* __restrict__ olo) {
    int row  = blockIdx.x;
    int lane = threadIdx.x & 31;
    int wid  = threadIdx.x >> 5;
    int c0   = wid * CH + (lane << 2);    // 4 contiguous channels

    float4 qv = *(const float4*)(q + (size_t)row * F + c0);

    float a0 = 0.f, a1 = 0.f, a2 = 0.f, a3 = 0.f;
    float m = NEG_BIG, s = 0.f;

    int start = rowptr[row], end = rowptr[row + 1];
    int i = start;
    while (i < end) {
        int rem = end - i;
        int c = rem < 4 ? rem : 4;
        int srcs[4];
        float dt[4];
#pragma unroll
        for (int j = 0; j < 4; j++)
            srcs[j] = csr[i + (j < c ? j : c - 1)];
#pragma unroll
        for (int j = 0; j < 4; j++) {
            uint2 kr = *(const uint2*)(kb + (size_t)srcs[j] * F + c0);
            float2 k01 = __bfloat1622float2(*(__nv_bfloat162*)&kr.x);
            float2 k23 = __bfloat1622float2(*(__nv_bfloat162*)&kr.y);
            dt[j] = qv.x * k01.x + qv.y * k01.y + qv.z * k23.x + qv.w * k23.y;
        }
#pragma unroll
        for (int o = 16; o >= 1; o >>= 1)
#pragma unroll
            for (int j = 0; j < 4; j++)
                dt[j] += __shfl_xor_sync(0xffffffffu, dt[j], o);

        float v0[4], v1[4], v2[4], v3[4];
#pragma unroll
        for (int j = 0; j < 4; j++) {
            uint2 vr = *(const uint2*)(vb + (size_t)srcs[j] * F + c0);
            float2 v01 = __bfloat1622float2(*(__nv_bfloat162*)&vr.x);
            float2 v23 = __bfloat1622float2(*(__nv_bfloat162*)&vr.y);
            v0[j] = v01.x; v1[j] = v01.y; v2[j] = v23.x; v3[j] = v23.y;
        }

#pragma unroll
        for (int j = 0; j < 4; j++)
            dt[j] = (j < c) ? dt[j] * 0.08838834764831845f : NEG_BIG;
        float cm = fmaxf(fmaxf(dt[0], dt[1]), fmaxf(dt[2], dt[3]));
        float mn = fmaxf(m, cm);
        float cf = __expf(m - mn);
        s *= cf; a0 *= cf; a1 *= cf; a2 *= cf; a3 *= cf;
#pragma unroll
        for (int j = 0; j < 4; j++) {
            if (j < c) {
                float p = __expf(dt[j] - mn);
                s += p;
                a0 += p * v0[j]; a1 += p * v1[j];
                a2 += p * v2[j]; a3 += p * v3[j];
            }
        }
        m = mn;
        i += c;
    }

    float inv = 1.0f / (s + 1e-16f);

    if constexpr (CONCAT) {
        float4 sp = *(const float4*)(skip + (size_t)row * F + c0);
        float r0 = fmaxf(sp.x + a0 * inv, 0.f);
        float r1 = fmaxf(sp.y + a1 * inv, 0.f);
        float r2 = fmaxf(sp.z + a2 * inv, 0.f);
        float r3 = fmaxf(sp.w + a3 * inv, 0.f);
        __nv_bfloat162 h01, h23, l01, l23;
        h01.x = __float2bfloat16_rn(r0); h01.y = __float2bfloat16_rn(r1);
        h23.x = __float2bfloat16_rn(r2); h23.y = __float2bfloat16_rn(r3);
        l01.x = __float2bfloat16_rn(r0 - __bfloat162float(h01.x));
        l01.y = __float2bfloat16_rn(r1 - __bfloat162float(h01.y));
        l23.x = __float2bfloat16_rn(r2 - __bfloat162float(h23.x));
        l23.y = __float2bfloat16_rn(r3 - __bfloat162float(h23.y));
        size_t ob = (size_t)row * F + c0;
        uint2 hh, ll;
        hh.x = *(unsigned*)&h01; hh.y = *(unsigned*)&h23;
        ll.x = *(unsigned*)&l01; ll.y = *(unsigned*)&l23;
        *(uint2*)(ohi + ob) = hh;
        *(uint2*)(olo + ob) = ll;
    } else {
        __shared__ __align__(16) float sh[F];
        float4 r;
        r.x = a0 * inv; r.y = a1 * inv; r.z = a2 * inv; r.w = a3 * inv;
        *(float4*)&sh[c0] = r;
        __syncthreads();
        int t = threadIdx.x;
        float sum = (sh[t] + sh[CH + t] + sh[2 * CH + t] + sh[3 * CH + t]) * 0.25f;
        out[(size_t)row * CH + t] += sum;
    }
}

// ---------------- launch -----------------------------------------------------
extern "C" void kernel_launch(void* const* d_in, const int* in_sizes, int n_in,
                              void* d_out, int out_size) {
    const float* x   = (const float*)d_in[0];
    const int*   ei  = (const int*)d_in[1];
    const float* Wq0 = (const float*)d_in[2];
    const float* bq0 = (const float*)d_in[3];
    const float* Wk0 = (const float*)d_in[4];
    const float* bk0 = (const float*)d_in[5];
    const float* Wv0 = (const float*)d_in[6];
    const float* bv0 = (const float*)d_in[7];
    const float* Ws0 = (const float*)d_in[8];
    const float* bs0 = (const float*)d_in[9];
    const float* Wq1 = (const float*)d_in[10];
    const float* bq1 = (const float*)d_in[11];
    const float* Wk1 = (const float*)d_in[12];
    const float* bk1 = (const float*)d_in[13];
    const float* Wv1 = (const float*)d_in[14];
    const float* bv1 = (const float*)d_in[15];
    const float* Ws1 = (const float*)d_in[16];
    const float* bs1 = (const float*)d_in[17];

    int N = in_sizes[0] / 128;     // 20000
    int E = in_sizes[1] / 2;       // 320000
    float* out = (float*)d_out;

    float *q, *h;
    __nv_bfloat16 *kb, *vb, *xhi, *xlo, *hhi, *hlo, *wh, *wl;
    int *deg, *rowptr, *cursor, *csr;
    cudaGetSymbolAddress((void**)&q, g_q);
    cudaGetSymbolAddress((void**)&kb, g_kb);
    cudaGetSymbolAddress((void**)&vb, g_vb);
    cudaGetSymbolAddress((void**)&h, g_h);
    cudaGetSymbolAddress((void**)&xhi, g_xhi);
    cudaGetSymbolAddress((void**)&xlo, g_xlo);
    cudaGetSymbolAddress((void**)&hhi, g_hhi);
    cudaGetSymbolAddress((void**)&hlo, g_hlo);
    cudaGetSymbolAddress((void**)&wh, g_wh);
    cudaGetSymbolAddress((void**)&wl, g_wl);
    cudaGetSymbolAddress((void**)&deg, g_deg);
    cudaGetSymbolAddress((void**)&rowptr, g_rowptr);
    cudaGetSymbolAddress((void**)&cursor, g_cursor);
    cudaGetSymbolAddress((void**)&csr, g_csr);

    cudaFuncSetAttribute(gemm_tc_kernel, cudaFuncAttributeMaxDynamicSharedMemorySize, GEMM_SMEM);

    // ---- CSR build ----
    cudaMemsetAsync(deg, 0, N * sizeof(int));
    count_kernel<<<(E + 255) / 256, 256>>>(ei, deg, E);
    scan_kernel<<<1, 1024>>>(deg, rowptr, cursor, N);
    fill_kernel<<<(E + 255) / 256, 256>>>(ei, cursor, csr, E);

    // ---- batched hi/lo splits (x + 8 weight matrices) ----
    {
        SplitBatch sb;
        sb.in[0] = x;   sb.hi[0] = xhi;      sb.lo[0] = xlo;      sb.n4[0] = (N * 128) / 4;
        sb.in[1] = Wq0; sb.hi[1] = wh + OQ0; sb.lo[1] = wl + OQ0; sb.n4[1] = 65536 / 4;
        sb.in[2] = Wk0; sb.hi[2] = wh + OK0; sb.lo[2] = wl + OK0; sb.n4[2] = 65536 / 4;
        sb.in[3] = Wv0; sb.hi[3] = wh + OV0; sb.lo[3] = wl + OV0; sb.n4[3] = 65536 / 4;
        sb.in[4] = Ws0; sb.hi[4] = wh + OS0; sb.lo[4] = wl + OS0; sb.n4[4] = 65536 / 4;
        sb.in[5] = Wq1; sb.hi[5] = wh + OQ1; sb.lo[5] = wl + OQ1; sb.n4[5] = 262144 / 4;
        sb.in[6] = Wk1; sb.hi[6] = wh + OK1; sb.lo[6] = wl + OK1; sb.n4[6] = 262144 / 4;
        sb.in[7] = Wv1; sb.hi[7] = wh + OV1; sb.lo[7] = wl + OV1; sb.n4[7] = 262144 / 4;
        sb.in[8] = Ws1; sb.hi[8] = wh + OS1; sb.lo[8] = wl + OS1; sb.n4[8] = 65536 / 4;
        int maxb = ((N * 128) / 4 + 255) / 256;
        dim3 grid(maxb, 1, 9);
        splitb_kernel<<<grid, 256>>>(sb);
    }

    int gy = (N + BM - 1) / BM;    // 157

    // ---- Layer 0: q,k,v,skip in ONE z-batched launch (K=128, N=512) ----
    {
        GemmBatch b;
        b.Ah = xhi; b.Al = xlo;
        b.Wh[0] = wh + OQ0; b.Wl[0] = wl + OQ0; b.bias[0] = bq0; b.C[0] = q;
        b.Wh[1] = wh + OK0; b.Wl[1] = wl + OK0; b.bias[1] = bk0; b.C[1] = kb;
        b.Wh[2] = wh + OV0; b.Wl[2] = wl + OV0; b.bias[2] = bv0; b.C[2] = vb;
        b.Wh[3] = wh + OS0; b.Wl[3] = wl + OS0; b.bias[3] = bs0; b.C[3] = h;
        b.bfmask = 0b0110u;
        dim3 grid(F / BN, gy, 4);
        gemm_tc_kernel<<<grid, 256, GEMM_SMEM>>>(b, N, 128, F);
    }
    agg_kernel<true><<<N, 128>>>(q, kb, vb, rowptr, csr, h, nullptr, hhi, hlo);

    // ---- Layer 1: q,k,v (K=512, N=512) z-batched + skip (N=128) ----
    {
        GemmBatch b;
        b.Ah = hhi; b.Al = hlo;
        b.Wh[0] = wh + OQ1; b.Wl[0] = wl + OQ1; b.bias[0] = bq1; b.C[0] = q;
        b.Wh[1] = wh + OK1; b.Wl[1] = wl + OK1; b.bias[1] = bk1; b.C[1] = kb;
        b.Wh[2] = wh + OV1; b.Wl[2] = wl + OV1; b.bias[2] = bv1; b.C[2] = vb;
        b.Wh[3] = wh + OQ1; b.Wl[3] = wl + OQ1; b.bias[3] = bq1; b.C[3] = q;  // unused
        b.bfmask = 0b0110u;
        dim3 grid(F / BN, gy, 3);
        gemm_tc_kernel<<<grid, 256, GEMM_SMEM>>>(b, N, F, F);
    }
    {
        GemmBatch b;
        b.Ah = hhi; b.Al = hlo;
        b.Wh[0] = wh + OS1; b.Wl[0] = wl + OS1; b.bias[0] = bs1; b.C[0] = out;
        b.Wh[1] = wh + OS1; b.Wl[1] = wl + OS1; b.bias[1] = bs1; b.C[1] = out;
        b.Wh[2] = wh + OS1; b.Wl[2] = wl + OS1; b.bias[2] = bs1; b.C[2] = out;
        b.Wh[3] = wh + OS1; b.Wl[3] = wl + OS1; b.bias[3] = bs1; b.C[3] = out;
        b.bfmask = 0u;
        dim3 grid(CH / BN, gy, 1);
        gemm_tc_kernel<<<grid, 256, GEMM_SMEM>>>(b, N, F, CH);
    }
    agg_kernel<false><<<N, 128>>>(q, kb, vb, rowptr, csr, nullptr, out, nullptr, nullptr);
}

// round 11
// speedup vs baseline: 3.7560x; 1.2565x over previous
#include <cuda_runtime.h>
#include <cuda_fp16.h>
#include <cuda_bf16.h>
#include <cstdint>

// Problem constants
#define MAXN 20000
#define MAXE 320000
#define F 512
#define CH 128
#define NEG_BIG (-3.402823466e38f)

// weight offsets in packed fp16 weight scratch (elements)
#define OQ0 0
#define OK0 65536
#define OV0 131072
#define OS0 196608
#define OQ1 262144
#define OK1 524288
#define OV1 786432
#define OS1 1048576
#define WTOT 1114112

// ---------------- device scratch ---------------------------------------------
__device__ float  g_q[MAXN * F];          // q (fp32, both layers)
__device__ __half g_kh[MAXN * F];         // k (fp16)
__device__ __half g_vh[MAXN * F];         // v (fp16)
__device__ float  g_h[MAXN * F];          // layer-0 skip (fp32)
__device__ __half g_xhi[MAXN * 128];
__device__ __half g_xlo[MAXN * 128];
__device__ __half g_hhi[MAXN * F];
__device__ __half g_hlo[MAXN * F];
__device__ __half g_wf[WTOT];             // all 8 weights, single fp16
__device__ int g_deg[MAXN];
__device__ int g_rowptr[MAXN + 1];
__device__ int g_cursor[MAXN];
__device__ int g_csr[MAXE];

// ---------------- CSR build --------------------------------------------------
__global__ void count_kernel(const int* __restrict__ ei, int* __restrict__ deg, int E) {
    int e = blockIdx.x * blockDim.x + threadIdx.x;
    if (e < E) atomicAdd(&deg[ei[E + e]], 1);
}

__global__ void scan_kernel(const int* __restrict__ deg, int* __restrict__ rowptr,
                            int* __restrict__ cursor, int n) {
    __shared__ int sh[1024];
    __shared__ int s_carry;
    if (threadIdx.x == 0) { s_carry = 0; rowptr[0] = 0; }
    __syncthreads();
    for (int base = 0; base < n; base += 1024) {
        int i = base + threadIdx.x;
        int v = (i < n) ? deg[i] : 0;
        sh[threadIdx.x] = v;
        __syncthreads();
        for (int off = 1; off < 1024; off <<= 1) {
            int t = 0;
            if (threadIdx.x >= off) t = sh[threadIdx.x - off];
            __syncthreads();
            if (threadIdx.x >= off) sh[threadIdx.x] += t;
            __syncthreads();
        }
        int incl = sh[threadIdx.x] + s_carry;
        if (i < n) {
            rowptr[i + 1] = incl;
            cursor[i] = incl - v;
        }
        __syncthreads();
        if (threadIdx.x == 0) s_carry += sh[1023];
        __syncthreads();
    }
}

__global__ void fill_kernel(const int* __restrict__ ei, int* __restrict__ cursor,
                            int* __restrict__ csr, int E) {
    int e = blockIdx.x * blockDim.x + threadIdx.x;
    if (e < E) {
        int dst = ei[E + e];
        int pos = atomicAdd(&cursor[dst], 1);
        csr[pos] = ei[e];   // store src id directly
    }
}

// ---------------- fp32 -> fp16 hi/lo split (A side) --------------------------
__global__ void split_kernel(const float* __restrict__ in,
                             __half* __restrict__ hi, __half* __restrict__ lo, int n4) {
    int i = blockIdx.x * blockDim.x + threadIdx.x;
    if (i >= n4) return;
    float4 v = ((const float4*)in)[i];
    __half2 h0, h1, l0, l1;
    h0.x = __float2half_rn(v.x); h0.y = __float2half_rn(v.y);
    h1.x = __float2half_rn(v.z); h1.y = __float2half_rn(v.w);
    l0.x = __float2half_rn(v.x - __half2float(h0.x));
    l0.y = __float2half_rn(v.y - __half2float(h0.y));
    l1.x = __float2half_rn(v.z - __half2float(h1.x));
    l1.y = __float2half_rn(v.w - __half2float(h1.y));
    uint2 hh, ll;
    hh.x = *(unsigned*)&h0; hh.y = *(unsigned*)&h1;
    ll.x = *(unsigned*)&l0; ll.y = *(unsigned*)&l1;
    ((uint2*)hi)[i] = hh;
    ((uint2*)lo)[i] = ll;
}

// ---------------- batched fp32 -> fp16 convert (weights) ---------------------
struct ConvBatch {
    const float* in[8];
    __half* out[8];
    int n4[8];
};

__global__ void convb_kernel(ConvBatch p) {
    int z = blockIdx.z;
    int i = blockIdx.x * blockDim.x + threadIdx.x;
    if (i >= p.n4[z]) return;
    float4 v = ((const float4*)p.in[z])[i];
    __half2 h0, h1;
    h0.x = __float2half_rn(v.x); h0.y = __float2half_rn(v.y);
    h1.x = __float2half_rn(v.z); h1.y = __float2half_rn(v.w);
    uint2 hh;
    hh.x = *(unsigned*)&h0; hh.y = *(unsigned*)&h1;
    ((uint2*)p.out[z])[i] = hh;
}

// ---------------- tensor-core GEMM (fp16x2 A, fp16 W, z-batched) -------------
// C[M,Nz] = A @ W + bias.  128x128x32 tiles, 256 thr, cp.async double-buffer.
// Per k16-step: acc += Ah*B; acc += Al*B  (2 MMAs).
#define BM 128
#define BN 128
#define BKK 32
#define A_STRIDE 40
#define B_STRIDE 136
// 2 stages * (2 * 128*40 halves A + 32*136 halves B) * 2B
#define GEMM_SMEM ((2 * (2 * BM * A_STRIDE + BKK * B_STRIDE)) * 2)   // 58368 B

__device__ __forceinline__ void mma_f16(float* d, const unsigned* a, const unsigned* b) {
    asm volatile(
        "mma.sync.aligned.m16n8k16.row.col.f32.f16.f16.f32 "
        "{%0,%1,%2,%3}, {%4,%5,%6,%7}, {%8,%9}, {%0,%1,%2,%3};"
        : "+f"(d[0]), "+f"(d[1]), "+f"(d[2]), "+f"(d[3])
        : "r"(a[0]), "r"(a[1]), "r"(a[2]), "r"(a[3]), "r"(b[0]), "r"(b[1]));
}
__device__ __forceinline__ void ldm_x4(unsigned* r, uint32_t addr) {
    asm volatile("ldmatrix.sync.aligned.m8n8.x4.shared.b16 {%0,%1,%2,%3}, [%4];"
                 : "=r"(r[0]), "=r"(r[1]), "=r"(r[2]), "=r"(r[3]) : "r"(addr));
}
__device__ __forceinline__ void ldm_x4_t(unsigned* r, uint32_t addr) {
    asm volatile("ldmatrix.sync.aligned.m8n8.x4.trans.shared.b16 {%0,%1,%2,%3}, [%4];"
                 : "=r"(r[0]), "=r"(r[1]), "=r"(r[2]), "=r"(r[3]) : "r"(addr));
}
__device__ __forceinline__ void cp16(uint32_t dst, const void* src, bool pred) {
    int sz = pred ? 16 : 0;
    asm volatile("cp.async.cg.shared.global [%0], [%1], 16, %2;\n"
                 :: "r"(dst), "l"(src), "r"(sz));
}
#define CP_COMMIT() asm volatile("cp.async.commit_group;\n" ::: "memory")
#define CP_WAIT(n)  asm volatile("cp.async.wait_group %0;\n" :: "n"(n) : "memory")

struct GemmBatch {
    const __half* Ah;
    const __half* Al;
    const __half* W[4];
    const float* bias[4];
    void* C[4];
    int Nz[4];         // output width per z (W is [K, Nz])
    unsigned hmask;    // bit z set -> output fp16, else fp32
};

__global__ __launch_bounds__(256, 2)
void gemm_tc_kernel(GemmBatch p, int M, int K) {
    extern __shared__ __half smem[];
    __half* As_hi = smem;                              // [2][BM][A_STRIDE]
    __half* As_lo = As_hi + 2 * BM * A_STRIDE;
    __half* Bs    = As_lo + 2 * BM * A_STRIDE;         // [2][BKK][B_STRIDE]

    int z = blockIdx.z;
    int N = p.Nz[z];
    int block_col = blockIdx.x * BN;
    if (block_col >= N) return;    // merged batch with smaller N: idle CTA exits

    const __half* Ah = p.Ah;
    const __half* Al = p.Al;
    const __half* W = p.W[z];
    const float* bias = p.bias[z];
    bool ohf = (p.hmask >> z) & 1u;
    float* Cf = (float*)p.C[z];
    __half* Chp = (__half*)p.C[z];

    int tid  = threadIdx.x;
    int lane = tid & 31;
    int wid  = tid >> 5;
    int warp_m = (wid >> 2) * 64;
    int warp_n = (wid & 3) * 32;
    int block_row = blockIdx.y * BM;

    float acc[4][4][4];
#pragma unroll
    for (int mi = 0; mi < 4; mi++)
#pragma unroll
        for (int ni = 0; ni < 4; ni++)
#pragma unroll
            for (int r = 0; r < 4; r++) acc[mi][ni][r] = 0.f;

    int Kt = K / BKK;

    auto load_stage = [&](int s, int kt) {
        int k0 = kt * BKK;
        __half* ah = As_hi + s * BM * A_STRIDE;
        __half* al = As_lo + s * BM * A_STRIDE;
        __half* bb = Bs + s * BKK * B_STRIDE;
#pragma unroll
        for (int l = 0; l < 2; l++) {
            int idx = tid + 256 * l;            // 0..511
            int ar = idx >> 2;                  // 0..127
            int ac = (idx & 3) * 8;             // 0..24
            int gr = block_row + ar;
            bool ok = gr < M;
            size_t go = (size_t)gr * K + k0 + ac;
            cp16((uint32_t)__cvta_generic_to_shared(&ah[ar * A_STRIDE + ac]), Ah + go, ok);
            cp16((uint32_t)__cvta_generic_to_shared(&al[ar * A_STRIDE + ac]), Al + go, ok);
            int kr = idx >> 4;                  // 0..31
            int nc = (idx & 15) * 8;            // 0..120
            size_t wo = (size_t)(k0 + kr) * N + block_col + nc;
            cp16((uint32_t)__cvta_generic_to_shared(&bb[kr * B_STRIDE + nc]), W + wo, true);
        }
    };

    load_stage(0, 0);
    CP_COMMIT();

    for (int kt = 0; kt < Kt; kt++) {
        int s = kt & 1;
        if (kt + 1 < Kt) {
            load_stage((kt + 1) & 1, kt + 1);
            CP_COMMIT();
            CP_WAIT(1);
        } else {
            CP_WAIT(0);
        }
        __syncthreads();

        const __half* ah_s = As_hi + s * BM * A_STRIDE;
        const __half* al_s = As_lo + s * BM * A_STRIDE;
        const __half* b_s  = Bs + s * BKK * B_STRIDE;

#pragma unroll
        for (int ks = 0; ks < 2; ks++) {
            int kk = ks * 16;
            unsigned bf[8];
#pragma unroll
            for (int nn = 0; nn < 2; nn++) {
                int qd = lane >> 3;
                int kr = kk + (qd & 1) * 8 + (lane & 7);
                int nc = warp_n + nn * 16 + (qd >> 1) * 8;
                ldm_x4_t(&bf[nn * 4], (uint32_t)__cvta_generic_to_shared(&b_s[kr * B_STRIDE + nc]));
            }
#pragma unroll
            for (int mi = 0; mi < 4; mi++) {
                int r = warp_m + mi * 16 + (lane & 15);
                int c = kk + (lane >> 4) * 8;
                unsigned ah[4], al[4];
                ldm_x4(ah, (uint32_t)__cvta_generic_to_shared(&ah_s[r * A_STRIDE + c]));
                ldm_x4(al, (uint32_t)__cvta_generic_to_shared(&al_s[r * A_STRIDE + c]));
#pragma unroll
                for (int ni = 0; ni < 4; ni++) {
                    mma_f16(acc[mi][ni], ah, &bf[ni * 2]);
                    mma_f16(acc[mi][ni], al, &bf[ni * 2]);
                }
            }
        }
        __syncthreads();
    }

    // epilogue: bias + store (fp32 or fp16 per z)
    int g  = lane >> 2;
    int tg = lane & 3;
#pragma unroll
    for (int mi = 0; mi < 4; mi++) {
#pragma unroll
        for (int ni = 0; ni < 4; ni++) {
            int col = block_col + warp_n + ni * 8 + tg * 2;
            float b0 = bias[col], b1 = bias[col + 1];
            int row0 = block_row + warp_m + mi * 16 + g;
            int row1 = row0 + 8;
            float o00 = acc[mi][ni][0] + b0, o01 = acc[mi][ni][1] + b1;
            float o10 = acc[mi][ni][2] + b0, o11 = acc[mi][ni][3] + b1;
            if (ohf) {
                if (row0 < M) {
                    __half2 pr; pr.x = __float2half_rn(o00); pr.y = __float2half_rn(o01);
                    *(__half2*)(Chp + (size_t)row0 * N + col) = pr;
                }
                if (row1 < M) {
                    __half2 pr; pr.x = __float2half_rn(o10); pr.y = __float2half_rn(o11);
                    *(__half2*)(Chp + (size_t)row1 * N + col) = pr;
                }
            } else {
                if (row0 < M) {
                    float2 o; o.x = o00; o.y = o01;
                    *(float2*)(Cf + (size_t)row0 * N + col) = o;
                }
                if (row1 < M) {
                    float2 o; o.x = o10; o.y = o11;
                    *(float2*)(Cf + (size_t)row1 * N + col) = o;
                }
            }
        }
    }
}

// ---------------- fused attention aggregation --------------------------------
// One block per dst node, 128 threads (warp = head). Lane owns 4 contiguous
// channels; k/v are fp16 (one 8B load per lane per row).
template <bool CONCAT>
__global__ __launch_bounds__(128)
void agg_kernel(const float* __restrict__ q, const __half* __restrict__ kh,
                const __half* __restrict__ vh,
                const int* __restrict__ rowptr, const int* __restrict__ csr,
                const float* __restrict__ skip,
                float* __restrict__ out,
                __half* __restrict__ ohi, __half* __restrict__ olo) {
    int row  = blockIdx.x;
    int lane = threadIdx.x & 31;
    int wid  = threadIdx.x >> 5;
    int c0   = wid * CH + (lane << 2);    // 4 contiguous channels

    float4 qv = *(const float4*)(q + (size_t)row * F + c0);

    float a0 = 0.f, a1 = 0.f, a2 = 0.f, a3 = 0.f;
    float m = NEG_BIG, s = 0.f;

    int start = rowptr[row], end = rowptr[row + 1];
    int i = start;
    while (i < end) {
        int rem = end - i;
        int c = rem < 4 ? rem : 4;
        int srcs[4];
        float dt[4];
#pragma unroll
        for (int j = 0; j < 4; j++)
            srcs[j] = csr[i + (j < c ? j : c - 1)];
#pragma unroll
        for (int j = 0; j < 4; j++) {
            uint2 kr = *(const uint2*)(kh + (size_t)srcs[j] * F + c0);
            float2 k01 = __half22float2(*(__half2*)&kr.x);
            float2 k23 = __half22float2(*(__half2*)&kr.y);
            dt[j] = qv.x * k01.x + qv.y * k01.y + qv.z * k23.x + qv.w * k23.y;
        }
#pragma unroll
        for (int o = 16; o >= 1; o >>= 1)
#pragma unroll
            for (int j = 0; j < 4; j++)
                dt[j] += __shfl_xor_sync(0xffffffffu, dt[j], o);

        float v0[4], v1[4], v2[4], v3[4];
#pragma unroll
        for (int j = 0; j < 4; j++) {
            uint2 vr = *(const uint2*)(vh + (size_t)srcs[j] * F + c0);
            float2 v01 = __half22float2(*(__half2*)&vr.x);
            float2 v23 = __half22float2(*(__half2*)&vr.y);
            v0[j] = v01.x; v1[j] = v01.y; v2[j] = v23.x; v3[j] = v23.y;
        }

#pragma unroll
        for (int j = 0; j < 4; j++)
            dt[j] = (j < c) ? dt[j] * 0.08838834764831845f : NEG_BIG;
        float cm = fmaxf(fmaxf(dt[0], dt[1]), fmaxf(dt[2], dt[3]));
        float mn = fmaxf(m, cm);
        float cf = __expf(m - mn);
        s *= cf; a0 *= cf; a1 *= cf; a2 *= cf; a3 *= cf;
#pragma unroll
        for (int j = 0; j < 4; j++) {
            if (j < c) {
                float p = __expf(dt[j] - mn);
                s += p;
                a0 += p * v0[j]; a1 += p * v1[j];
                a2 += p * v2[j]; a3 += p * v3[j];
            }
        }
        m = mn;
        i += c;
    }

    float inv = 1.0f / (s + 1e-16f);

    if constexpr (CONCAT) {
        float4 sp = *(const float4*)(skip + (size_t)row * F + c0);
        float r0 = fmaxf(sp.x + a0 * inv, 0.f);
        float r1 = fmaxf(sp.y + a1 * inv, 0.f);
        float r2 = fmaxf(sp.z + a2 * inv, 0.f);
        float r3 = fmaxf(sp.w + a3 * inv, 0.f);
        __half2 h01, h23, l01, l23;
        h01.x = __float2half_rn(r0); h01.y = __float2half_rn(r1);
        h23.x = __float2half_rn(r2); h23.y = __float2half_rn(r3);
        l01.x = __float2half_rn(r0 - __half2float(h01.x));
        l01.y = __float2half_rn(r1 - __half2float(h01.y));
        l23.x = __float2half_rn(r2 - __half2float(h23.x));
        l23.y = __float2half_rn(r3 - __half2float(h23.y));
        size_t ob = (size_t)row * F + c0;
        uint2 hh, ll;
        hh.x = *(unsigned*)&h01; hh.y = *(unsigned*)&h23;
        ll.x = *(unsigned*)&l01; ll.y = *(unsigned*)&l23;
        *(uint2*)(ohi + ob) = hh;
        *(uint2*)(olo + ob) = ll;
    } else {
        __shared__ __align__(16) float sh[F];
        float4 r;
        r.x = a0 * inv; r.y = a1 * inv; r.z = a2 * inv; r.w = a3 * inv;
        *(float4*)&sh[c0] = r;
        __syncthreads();
        int t = threadIdx.x;
        float sum = (sh[t] + sh[CH + t] + sh[2 * CH + t] + sh[3 * CH + t]) * 0.25f;
        out[(size_t)row * CH + t] += sum;
    }
}

// ---------------- launch -----------------------------------------------------
extern "C" void kernel_launch(void* const* d_in, const int* in_sizes, int n_in,
                              void* d_out, int out_size) {
    const float* x   = (const float*)d_in[0];
    const int*   ei  = (const int*)d_in[1];
    const float* Wq0 = (const float*)d_in[2];
    const float* bq0 = (const float*)d_in[3];
    const float* Wk0 = (const float*)d_in[4];
    const float* bk0 = (const float*)d_in[5];
    const float* Wv0 = (const float*)d_in[6];
    const float* bv0 = (const float*)d_in[7];
    const float* Ws0 = (const float*)d_in[8];
    const float* bs0 = (const float*)d_in[9];
    const float* Wq1 = (const float*)d_in[10];
    const float* bq1 = (const float*)d_in[11];
    const float* Wk1 = (const float*)d_in[12];
    const float* bk1 = (const float*)d_in[13];
    const float* Wv1 = (const float*)d_in[14];
    const float* bv1 = (const float*)d_in[15];
    const float* Ws1 = (const float*)d_in[16];
    const float* bs1 = (const float*)d_in[17];

    int N = in_sizes[0] / 128;     // 20000
    int E = in_sizes[1] / 2;       // 320000
    float* out = (float*)d_out;

    float *q, *h;
    __half *kh, *vh, *xhi, *xlo, *hhi, *hlo, *wf;
    int *deg, *rowptr, *cursor, *csr;
    cudaGetSymbolAddress((void**)&q, g_q);
    cudaGetSymbolAddress((void**)&kh, g_kh);
    cudaGetSymbolAddress((void**)&vh, g_vh);
    cudaGetSymbolAddress((void**)&h, g_h);
    cudaGetSymbolAddress((void**)&xhi, g_xhi);
    cudaGetSymbolAddress((void**)&xlo, g_xlo);
    cudaGetSymbolAddress((void**)&hhi, g_hhi);
    cudaGetSymbolAddress((void**)&hlo, g_hlo);
    cudaGetSymbolAddress((void**)&wf, g_wf);
    cudaGetSymbolAddress((void**)&deg, g_deg);
    cudaGetSymbolAddress((void**)&rowptr, g_rowptr);
    cudaGetSymbolAddress((void**)&cursor, g_cursor);
    cudaGetSymbolAddress((void**)&csr, g_csr);

    cudaFuncSetAttribute(gemm_tc_kernel, cudaFuncAttributeMaxDynamicSharedMemorySize, GEMM_SMEM);

    // ---- CSR build ----
    cudaMemsetAsync(deg, 0, N * sizeof(int));
    count_kernel<<<(E + 255) / 256, 256>>>(ei, deg, E);
    scan_kernel<<<1, 1024>>>(deg, rowptr, cursor, N);
    fill_kernel<<<(E + 255) / 256, 256>>>(ei, cursor, csr, E);

    // ---- x hi/lo split ----
    {
        int n4 = (N * 128) / 4;
        split_kernel<<<(n4 + 255) / 256, 256>>>(x, xhi, xlo, n4);
    }
    // ---- weight fp16 converts, z-batched ----
    {
        ConvBatch cb;
        cb.in[0] = Wq0; cb.out[0] = wf + OQ0; cb.n4[0] = 65536 / 4;
        cb.in[1] = Wk0; cb.out[1] = wf + OK0; cb.n4[1] = 65536 / 4;
        cb.in[2] = Wv0; cb.out[2] = wf + OV0; cb.n4[2] = 65536 / 4;
        cb.in[3] = Ws0; cb.out[3] = wf + OS0; cb.n4[3] = 65536 / 4;
        cb.in[4] = Wq1; cb.out[4] = wf + OQ1; cb.n4[4] = 262144 / 4;
        cb.in[5] = Wk1; cb.out[5] = wf + OK1; cb.n4[5] = 262144 / 4;
        cb.in[6] = Wv1; cb.out[6] = wf + OV1; cb.n4[6] = 262144 / 4;
        cb.in[7] = Ws1; cb.out[7] = wf + OS1; cb.n4[7] = 65536 / 4;
        dim3 grid((262144 / 4 + 255) / 256, 1, 8);
        convb_kernel<<<grid, 256>>>(cb);
    }

    int gy = (N + BM - 1) / BM;    // 157

    // ---- Layer 0: q,k,v,skip in ONE z-batched launch (K=128, N=512) ----
    {
        GemmBatch b;
        b.Ah = xhi; b.Al = xlo;
        b.W[0] = wf + OQ0; b.bias[0] = bq0; b.C[0] = q;   b.Nz[0] = 512;
        b.W[1] = wf + OK0; b.bias[1] = bk0; b.C[1] = kh;  b.Nz[1] = 512;
        b.W[2] = wf + OV0; b.bias[2] = bv0; b.C[2] = vh;  b.Nz[2] = 512;
        b.W[3] = wf + OS0; b.bias[3] = bs0; b.C[3] = h;   b.Nz[3] = 512;
        b.hmask = 0b0110u;
        dim3 grid(F / BN, gy, 4);
        gemm_tc_kernel<<<grid, 256, GEMM_SMEM>>>(b, N, 128);
    }
    agg_kernel<true><<<N, 128>>>(q, kh, vh, rowptr, csr, h, nullptr, hhi, hlo);

    // ---- Layer 1: q,k,v (N=512) + skip (N=128) merged, K=512 ----
    {
        GemmBatch b;
        b.Ah = hhi; b.Al = hlo;
        b.W[0] = wf + OQ1; b.bias[0] = bq1; b.C[0] = q;   b.Nz[0] = 512;
        b.W[1] = wf + OK1; b.bias[1] = bk1; b.C[1] = kh;  b.Nz[1] = 512;
        b.W[2] = wf + OV1; b.bias[2] = bv1; b.C[2] = vh;  b.Nz[2] = 512;
        b.W[3] = wf + OS1; b.bias[3] = bs1; b.C[3] = out; b.Nz[3] = 128;
        b.hmask = 0b0110u;
        dim3 grid(F / BN, gy, 4);
        gemm_tc_kernel<<<grid, 256, GEMM_SMEM>>>(b, N, F);
    }
    agg_kernel<false><<<N, 128>>>(q, kh, vh, rowptr, csr, nullptr, out, nullptr, nullptr);
}